// round 13
// baseline (speedup 1.0000x reference)
#include <cuda_runtime.h>
#include <math.h>

#define NB     32
#define NPG1   256
#define NHID   64
#define KP1    128
#define KP2    64
#define NN1    (NB*NPG1)   // 8192
#define NN2    (NB*KP1)    // 4096
#define NN3    (NB*KP2)    // 2048
#define NCLS   6
#define PROJ_MAX 0.996f
#define MINN   1e-15f
#define AART   3.1063030f   // artanh(0.996)

#define NBLK 512
#define NTHR 256
#define NT   (NBLK*NTHR)    // 131072 threads
#define NW   (NT/32)        // 4096 warps

// ---------------- device scratch (de-aliased per layer: L1-coherence audit) ----------------
__device__ unsigned g_bm[NN1*8];       // zero at every kernel entry (invariant)
__device__ float g_s[NN1];
__device__ float g_u1[NN1*NHID];
__device__ float g_t1[NN1*NHID];
__device__ float g_dis1[NN1];
__device__ float g_sc1[NN1];
__device__ int   g_lidxA[NB*KP1];
__device__ float g_a1A[NB*KP1];
__device__ float g_a2A[NB*KP1];
__device__ float g_xn1[NN2*NHID];
__device__ float g_adj2[NB*KP1*KP1];
__device__ float g_u2[NN2*NHID];
__device__ float g_t2[NN2*NHID];
__device__ float g_dis2[NN2];
__device__ float g_sc2[NN2];
__device__ int   g_lidxB[NB*KP2];
__device__ float g_a1B[NB*KP2];
__device__ float g_a2B[NB*KP2];
__device__ float g_xn2[NN3*NHID];
__device__ float g_adj3[NB*KP2*KP2];
__device__ float g_u3[NN3*NHID];
__device__ float g_t3[NN3*NHID];
__device__ float g_dis3[NN3];
// grid barrier state
__device__ unsigned g_barc;
__device__ volatile unsigned g_barg;

// ---------------- helpers ----------------
__device__ __forceinline__ float artanh_(float x){
    x = fminf(fmaxf(x, -1.0f + 1e-7f), 1.0f - 1e-7f);
    return 0.5f*(log1pf(x) - log1pf(-x));
}
__device__ __forceinline__ float warpSum(float v){
    #pragma unroll
    for (int o = 16; o; o >>= 1) v += __shfl_xor_sync(0xffffffffu, v, o);
    return v;
}
__device__ __forceinline__ void gsync(){
    __syncthreads();
    if (threadIdx.x == 0){
        __threadfence();
        unsigned gen = g_barg;
        if (atomicAdd(&g_barc, 1u) == NBLK-1u){
            g_barc = 0u;
            __threadfence();
            g_barg = gen + 1u;
        } else {
            while (g_barg == gen) { }
        }
        __threadfence();
    }
    __syncthreads();
}

__device__ __forceinline__ void hyp_tail(float mx0, float mx1, float xn,
                                         const float* __restrict__ bb, int l,
                                         float* __restrict__ up){
    float mxn = fmaxf(sqrtf(warpSum(mx0*mx0 + mx1*mx1)), MINN);
    float tv  = tanhf(mxn/xn*artanh_(xn));
    float hs  = tv/mxn;
    float h0 = mx0*hs, h1 = mx1*hs;
    float hn = tv;
    if (hn > PROJ_MAX){ float c = PROJ_MAX/hn; h0 *= c; h1 *= c; hn = PROJ_MAX; }
    float x2 = hn*hn;
    float b0 = bb[l], b1 = bb[l+32];
    float bn = fmaxf(sqrtf(warpSum(b0*b0 + b1*b1)), MINN);
    float tb = tanhf(bn);
    float hbs = tb/bn, hbn = tb;
    if (tb > PROJ_MAX){ hbs = PROJ_MAX/bn; hbn = PROJ_MAX; }
    float hb0 = b0*hbs, hb1 = b1*hbs;
    float y2 = hbn*hbn;
    float xy = warpSum(h0*hb0 + h1*hb1);
    float ca = 1.f + 2.f*xy + y2, cb = 1.f - x2;
    float den = fmaxf(1.f + 2.f*xy + x2*y2, MINN);
    float r0 = (ca*h0 + cb*hb0)/den, r1 = (ca*h1 + cb*hb1)/den;
    float rn = fmaxf(sqrtf(warpSum(r0*r0 + r1*r1)), MINN);
    float pn = rn, psc = 1.f;
    if (rn > PROJ_MAX){ psc = PROJ_MAX/rn; pn = PROJ_MAX; }
    float ls = artanh_(pn)/pn*psc;
    up[l] = r0*ls; up[l+32] = r1*ls;
}

__device__ __forceinline__ void agg_epi(int node, float a0, float a1, float deg,
                                        float* __restrict__ tout, float* __restrict__ dis, int l){
    float n1 = sqrtf(warpSum(a0*a0 + a1*a1));
    float s1 = (n1 > AART) ? AART/n1 : 1.f;
    float w0 = fmaxf(a0*s1, 0.f), w1 = fmaxf(a1*s1, 0.f);
    float n2 = sqrtf(warpSum(w0*w0 + w1*w1));
    float s2 = (n2 > AART) ? AART/n2 : 1.f;
    tout[(size_t)node*64 + l]      = w0*s2;
    tout[(size_t)node*64 + l + 32] = w1*s2;
    if (l == 0) dis[node] = (deg > 0.f) ? rsqrtf(deg) : 0.f;
}

// dense agg tile: 16 rows per block (2 per warp), u staged in sbuf
template<int NPG>
__device__ void aggT_body(int blk, float* sbuf, const float* __restrict__ adj,
                          const float* __restrict__ u, float* __restrict__ tout,
                          float* __restrict__ dis){
    constexpr int TPG = NPG/16;
    int g = blk / TPG, rt = blk % TPG;
    int w = threadIdx.x >> 5, l = threadIdx.x & 31;
    int rbase = rt*16 + w*2;
    const float* adjg = adj + (size_t)g*NPG*NPG;
    const float* ug   = u   + (size_t)g*NPG*64;
    {
        const float4* src = (const float4*)ug;
        float4* dst = (float4*)sbuf;
        for (int e = threadIdx.x; e < NPG*16; e += NTHR) dst[e] = src[e];
    }
    __syncthreads();
    const float* r0p = adjg + (size_t)rbase*NPG;
    const float* r1p = r0p + NPG;
    float a00=0,a01=0,a10=0,a11=0,d0=0,d1=0;
    #pragma unroll 4
    for (int m = 0; m < NPG; m += 4){
        float4 v0 = *(const float4*)(r0p + m);
        float4 v1 = *(const float4*)(r1p + m);
        float ar0[4] = {v0.x, v0.y, v0.z, v0.w};
        float ar1[4] = {v1.x, v1.y, v1.z, v1.w};
        #pragma unroll
        for (int q = 0; q < 4; q++){
            float u0 = sbuf[(m+q)*64 + l];
            float u1 = sbuf[(m+q)*64 + l + 32];
            a00 += ar0[q]*u0; a01 += ar0[q]*u1; d0 += ar0[q];
            a10 += ar1[q]*u0; a11 += ar1[q]*u1; d1 += ar1[q];
        }
    }
    int nb = g*NPG + rbase;
    agg_epi(nb,   a00, a01, d0, tout, dis, l);
    agg_epi(nb+1, a10, a11, d1, tout, dis, l);
}

template<int NPG>
__device__ void scoreT_body(int blk, float* sbuf, const float* __restrict__ adj,
                            const float* __restrict__ t, const float* __restrict__ dis,
                            float* __restrict__ score){
    constexpr int TPG = NPG/16;
    int g = blk / TPG, rt = blk % TPG;
    int w = threadIdx.x >> 5, l = threadIdx.x & 31;
    int rbase = rt*16 + w*2;
    const float* adjg = adj + (size_t)g*NPG*NPG;
    const float* tg   = t   + (size_t)g*NPG*64;
    const float* disg = dis + (size_t)g*NPG;
    {
        const float4* src = (const float4*)tg;
        float4* dst = (float4*)sbuf;
        for (int e = threadIdx.x; e < NPG*16; e += NTHR){
            float4 v = src[e];
            float dm = disg[e >> 4];
            v.x *= dm; v.y *= dm; v.z *= dm; v.w *= dm;
            dst[e] = v;
        }
    }
    float tr0 = tg[(size_t)rbase*64 + l],     tr1 = tg[(size_t)rbase*64 + l + 32];
    float sr0 = tg[(size_t)(rbase+1)*64 + l], sr1 = tg[(size_t)(rbase+1)*64 + l + 32];
    float dr0 = disg[rbase], dr1 = disg[rbase+1];
    __syncthreads();
    const float* r0p = adjg + (size_t)rbase*NPG;
    const float* r1p = r0p + NPG;
    float a00=0,a01=0,a10=0,a11=0;
    #pragma unroll 4
    for (int m = 0; m < NPG; m += 4){
        float4 v0 = *(const float4*)(r0p + m);
        float4 v1 = *(const float4*)(r1p + m);
        float ar0[4] = {v0.x, v0.y, v0.z, v0.w};
        float ar1[4] = {v1.x, v1.y, v1.z, v1.w};
        #pragma unroll
        for (int q = 0; q < 4; q++){
            float u0 = sbuf[(m+q)*64 + l];
            float u1 = sbuf[(m+q)*64 + l + 32];
            a00 += ar0[q]*u0; a01 += ar0[q]*u1;
            a10 += ar1[q]*u0; a11 += ar1[q]*u1;
        }
    }
    float d0 = fabsf(tr0 - dr0*a00) + fabsf(tr1 - dr0*a01);
    float d1 = fabsf(sr0 - dr1*a10) + fabsf(sr1 - dr1*a11);
    float sc0 = warpSum(d0), sc1 = warpSum(d1);
    if (l == 0){ score[g*NPG + rbase] = sc0; score[g*NPG + rbase + 1] = sc1; }
}

// ---------------- THE kernel ----------------
__global__ void __launch_bounds__(NTHR, 4)
k_all(const float* __restrict__ x, const int* __restrict__ ei, int E,
      const float* __restrict__ W1, const float* __restrict__ b1,
      const float* __restrict__ W2, const float* __restrict__ b2,
      const float* __restrict__ W3, const float* __restrict__ b3,
      const float* __restrict__ att1, const float* __restrict__ att2,
      const float* __restrict__ lw1, const float* __restrict__ lb1,
      const float* __restrict__ lw2, const float* __restrict__ lb2,
      const float* __restrict__ lw3, const float* __restrict__ lb3,
      float* __restrict__ out)
{
    __shared__ float sbuf[8192];   // 32 KB, aliased per stage
    const int tid = threadIdx.x;
    const int gtid = blockIdx.x*NTHR + tid;
    const int gw = gtid >> 5;
    const int l = tid & 31;

    unsigned* bm = g_bm;

    // ---- S1: edge scatter (bm pre-zeroed invariant) || prep1 (row sums + to_hyp + HypLinear L1)
    for (int e = gtid; e < E; e += NT){
        int r = ei[e], c = ei[E + e];
        int lc = c & 255;
        atomicOr(&bm[(size_t)r*8 + (lc >> 5)], 1u << (lc & 31));
    }
    for (int e = tid; e < 128*64; e += NTHR){
        int j = e >> 7, k = e & 127;
        sbuf[k*64 + j] = W1[e];
    }
    __syncthreads();
    for (int node = gw; node < NN1; node += NW){
        const float* xp = x + (size_t)node*128;
        float xq[4];
        #pragma unroll
        for (int q = 0; q < 4; q++) xq[q] = xp[l + 32*q];
        float ssum = warpSum(xq[0]+xq[1]+xq[2]+xq[3]);
        if (l == 0) g_s[node] = ssum;
        float n0 = fmaxf(sqrtf(warpSum(xq[0]*xq[0]+xq[1]*xq[1]+xq[2]*xq[2]+xq[3]*xq[3])), MINN);
        float th = tanhf(n0);
        float xsc, xn;
        if (th > PROJ_MAX){ xsc = PROJ_MAX/n0; xn = PROJ_MAX; } else { xsc = th/n0; xn = th; }
        xn = fmaxf(xn, MINN);
        #pragma unroll
        for (int q = 0; q < 4; q++) xq[q] *= xsc;
        float mx0 = 0.f, mx1 = 0.f;
        #pragma unroll
        for (int q = 0; q < 4; q++){
            float xv = xq[q];
            for (int kk = 0; kk < 32; kk++){
                float xk = __shfl_sync(0xffffffffu, xv, kk);
                int k = q*32 + kk;
                mx0 += xk*sbuf[k*64 + l];
                mx1 += xk*sbuf[k*64 + l + 32];
            }
        }
        hyp_tail(mx0, mx1, xn, b1, l, g_u1 + (size_t)node*64);
    }
    gsync();

    // ---- S2: sparse agg layer1
    for (int node = gw; node < NN1; node += NW){
        int g = node >> 8;
        const float* ug = g_u1 + ((size_t)(g << 8))*64;
        const float* sg = g_s + (g << 8);
        float sn = sg[node & 255];
        float a0 = 0.f, a1 = 0.f, deg = 0.f;
        #pragma unroll
        for (int w8 = 0; w8 < 8; w8++){
            unsigned bits = bm[(size_t)node*8 + w8];
            while (bits){
                int b = __ffs(bits) - 1; bits &= bits - 1;
                int c = (w8 << 5) | b;
                float wv = 0.5f*(sn + sg[c]);
                a0 += wv*ug[(size_t)c*64 + l];
                a1 += wv*ug[(size_t)c*64 + l + 32];
                deg += wv;
            }
        }
        agg_epi(node, a0, a1, deg, g_t1, g_dis1, l);
    }
    gsync();

    // ---- S3: sparse score layer1
    for (int node = gw; node < NN1; node += NW){
        int g = node >> 8;
        const float* tg = g_t1 + ((size_t)(g << 8))*64;
        const float* sg = g_s + (g << 8);
        const float* dg = g_dis1 + (g << 8);
        float sn = sg[node & 255];
        float dn = dg[node & 255];
        float a0 = 0.f, a1 = 0.f;
        #pragma unroll
        for (int w8 = 0; w8 < 8; w8++){
            unsigned bits = bm[(size_t)node*8 + w8];
            while (bits){
                int b = __ffs(bits) - 1; bits &= bits - 1;
                int c = (w8 << 5) | b;
                float wv = 0.5f*(sn + sg[c])*dg[c];
                a0 += wv*tg[(size_t)c*64 + l];
                a1 += wv*tg[(size_t)c*64 + l + 32];
            }
        }
        float tr0 = tg[(size_t)(node & 255)*64 + l];
        float tr1 = tg[(size_t)(node & 255)*64 + l + 32];
        float d = fabsf(tr0 - dn*a0) + fabsf(tr1 - dn*a1);
        float sc = warpSum(d);
        if (l == 0) g_sc1[node] = sc;
    }
    gsync();

    // ---- S4: rank-select layer1 (blocks 0..31, one graph each)
    if (blockIdx.x < NB){
        int g = blockIdx.x;
        float* key = sbuf; float* satt = sbuf + 256;
        key[tid] = g_sc1[g*256 + tid];
        if (tid < 128) satt[tid] = att1[tid];
        __syncthreads();
        float kt = key[tid];
        int rank = 0;
        #pragma unroll 8
        for (int p = 0; p < 256; p++){
            float kp = key[p];
            rank += (kp > kt || (kp == kt && p < tid)) ? 1 : 0;
        }
        if (rank < KP1){
            g_lidxA[g*KP1 + rank] = tid;
            float tv = tanhf(kt);
            const float* src = g_t1 + ((size_t)g*256 + tid)*64;
            float* dst = g_xn1 + ((size_t)g*KP1 + rank)*64;
            float d1 = 0.f, d2 = 0.f;
            #pragma unroll 8
            for (int j = 0; j < 64; j++){
                float v = src[j]*tv; dst[j] = v;
                d1 += v*satt[j]; d2 += v*satt[64 + j];
            }
            g_a1A[g*KP1 + rank] = d1; g_a2A[g*KP1 + rank] = d2;
        }
    }
    gsync();

    // ---- S5: adjb1 (bitmap lookup) || linear2
    for (int e = tid; e < 64*64; e += NTHR){
        int j = e >> 6, k = e & 63;
        sbuf[k*64 + j] = W2[e];
    }
    for (int e = gtid; e < NB*KP1*KP1; e += NT){
        int bi = e >> 7;            // g*128 + i
        int j  = e & 127;
        int g  = bi >> 7;
        int li = g_lidxA[bi];
        int lj = g_lidxA[(g << 7) + j];
        float ev = fmaxf(g_a1A[bi] + g_a2A[(g << 7) + j], 0.f);
        unsigned word = bm[((size_t)(g << 8) + li)*8 + (lj >> 5)];
        float old = ((word >> (lj & 31)) & 1u) ? 0.5f*(g_s[(g << 8) + li] + g_s[(g << 8) + lj]) : 0.f;
        g_adj2[(size_t)bi*128 + j] = ev + old;
    }
    __syncthreads();
    for (int node = gw; node < NN2; node += NW){
        const float* xp = g_xn1 + (size_t)node*64;
        float x0 = xp[l], x1 = xp[l+32];
        float n0 = fmaxf(sqrtf(warpSum(x0*x0 + x1*x1)), MINN);
        float th = tanhf(n0);
        float xsc, xn;
        if (th > PROJ_MAX){ xsc = PROJ_MAX/n0; xn = PROJ_MAX; } else { xsc = th/n0; xn = th; }
        xn = fmaxf(xn, MINN);
        x0 *= xsc; x1 *= xsc;
        float mx0 = 0.f, mx1 = 0.f;
        #pragma unroll
        for (int q = 0; q < 2; q++){
            float xv = q ? x1 : x0;
            for (int kk = 0; kk < 32; kk++){
                float xk = __shfl_sync(0xffffffffu, xv, kk);
                int k = q*32 + kk;
                mx0 += xk*sbuf[k*64 + l];
                mx1 += xk*sbuf[k*64 + l + 32];
            }
        }
        hyp_tail(mx0, mx1, xn, b2, l, g_u2 + (size_t)node*64);
    }
    gsync();

    // ---- S6: dense agg layer2 (256 tiles)
    if (blockIdx.x < NB*(KP1/16)) aggT_body<KP1>(blockIdx.x, sbuf, g_adj2, g_u2, g_t2, g_dis2);
    gsync();

    // ---- S7: dense score layer2
    if (blockIdx.x < NB*(KP1/16)) scoreT_body<KP1>(blockIdx.x, sbuf, g_adj2, g_t2, g_dis2, g_sc2);
    gsync();

    // ---- S8: rank-select layer2
    if (blockIdx.x < NB){
        int g = blockIdx.x;
        float* key = sbuf; float* satt = sbuf + 128;
        if (tid < 128){ key[tid] = g_sc2[g*128 + tid]; satt[tid] = att2[tid]; }
        __syncthreads();
        if (tid < 128){
            float kt = key[tid];
            int rank = 0;
            #pragma unroll 8
            for (int p = 0; p < 128; p++){
                float kp = key[p];
                rank += (kp > kt || (kp == kt && p < tid)) ? 1 : 0;
            }
            if (rank < KP2){
                g_lidxB[g*KP2 + rank] = tid;
                float tv = tanhf(kt);
                const float* src = g_t2 + ((size_t)g*128 + tid)*64;
                float* dst = g_xn2 + ((size_t)g*KP2 + rank)*64;
                float d1 = 0.f, d2 = 0.f;
                #pragma unroll 8
                for (int j = 0; j < 64; j++){
                    float v = src[j]*tv; dst[j] = v;
                    d1 += v*satt[j]; d2 += v*satt[64 + j];
                }
                g_a1B[g*KP2 + rank] = d1; g_a2B[g*KP2 + rank] = d2;
            }
        }
    }
    gsync();

    // ---- S9: adjb2 || linear3
    for (int e = tid; e < 64*64; e += NTHR){
        int j = e >> 6, k = e & 63;
        sbuf[k*64 + j] = W3[e];
    }
    for (int e = gtid; e < NB*KP2*KP2; e += NT){
        int bi = e >> 6;            // g*64 + i
        int j  = e & 63;
        int g  = bi >> 6;
        int li = g_lidxB[bi];
        int lj = g_lidxB[(g << 6) + j];
        float ev = fmaxf(g_a1B[bi] + g_a2B[(g << 6) + j], 0.f);
        float old = g_adj2[((size_t)(g << 7) + li)*128 + lj];
        g_adj3[(size_t)bi*64 + j] = ev + old;
    }
    __syncthreads();
    for (int node = gw; node < NN3; node += NW){
        const float* xp = g_xn2 + (size_t)node*64;
        float x0 = xp[l], x1 = xp[l+32];
        float n0 = fmaxf(sqrtf(warpSum(x0*x0 + x1*x1)), MINN);
        float th = tanhf(n0);
        float xsc, xn;
        if (th > PROJ_MAX){ xsc = PROJ_MAX/n0; xn = PROJ_MAX; } else { xsc = th/n0; xn = th; }
        xn = fmaxf(xn, MINN);
        x0 *= xsc; x1 *= xsc;
        float mx0 = 0.f, mx1 = 0.f;
        #pragma unroll
        for (int q = 0; q < 2; q++){
            float xv = q ? x1 : x0;
            for (int kk = 0; kk < 32; kk++){
                float xk = __shfl_sync(0xffffffffu, xv, kk);
                int k = q*32 + kk;
                mx0 += xk*sbuf[k*64 + l];
                mx1 += xk*sbuf[k*64 + l + 32];
            }
        }
        hyp_tail(mx0, mx1, xn, b3, l, g_u3 + (size_t)node*64);
    }
    gsync();

    // ---- S10: dense agg layer3 (128 tiles)
    if (blockIdx.x < NB*(KP2/16)) aggT_body<KP2>(blockIdx.x, sbuf, g_adj3, g_u3, g_t3, g_dis3);
    gsync();

    // ---- S11: readout + MLP + log_softmax (blocks 0..31) + bm reset (all blocks)
    if (blockIdx.x < NB){
        float* sA = sbuf;          // 256
        float* sB = sbuf + 256;    // 256
        float* rr = sbuf + 512;    // 128
        float* h1 = sbuf + 640;    // 64
        float* h2 = sbuf + 704;    // 32
        float* lg = sbuf + 736;    // 6
        int g = blockIdx.x;
        int f = tid & 63, grp = tid >> 6;
        float accM = 0.f, accE = 0.f;
        #pragma unroll
        for (int srci = 0; srci < 3; srci++){
            const float* base = (srci == 0) ? g_xn1 + (size_t)g*KP1*64
                              : (srci == 1) ? g_xn2 + (size_t)g*KP2*64
                                            : g_t3  + (size_t)g*KP2*64;
            int K = (srci == 0) ? KP1 : KP2;
            float pm = -3.402823466e38f, ps = 0.f;
            for (int i = grp; i < K; i += 4){
                float v = base[(size_t)i*64 + f];
                pm = fmaxf(pm, v); ps += v;
            }
            sA[grp*64 + f] = pm; sB[grp*64 + f] = ps;
            __syncthreads();
            if (tid < 64){
                float mx = fmaxf(fmaxf(sA[f], sA[64+f]), fmaxf(sA[128+f], sA[192+f]));
                float sm = sB[f] + sB[64+f] + sB[128+f] + sB[192+f];
                accM += fmaxf(mx, 0.f);
                accE += fmaxf(sm/(float)K, 0.f);
            }
            __syncthreads();
        }
        if (tid < 64){ rr[f] = accM; rr[64+f] = accE; }
        __syncthreads();
        if (tid < 64){
            float a = lb1[tid];
            #pragma unroll 8
            for (int q = 0; q < 128; q++) a += lw1[(size_t)tid*128 + q]*rr[q];
            h1[tid] = fmaxf(a, 0.f);
        }
        __syncthreads();
        if (tid < 32){
            float a = lb2[tid];
            #pragma unroll 8
            for (int q = 0; q < 64; q++) a += lw2[(size_t)tid*64 + q]*h1[q];
            h2[tid] = fmaxf(a, 0.f);
        }
        __syncthreads();
        if (tid < NCLS){
            float a = lb3[tid];
            #pragma unroll
            for (int q = 0; q < 32; q++) a += lw3[(size_t)tid*32 + q]*h2[q];
            lg[tid] = a;
        }
        __syncthreads();
        if (tid == 0){
            float mx = lg[0];
            for (int c = 1; c < NCLS; c++) mx = fmaxf(mx, lg[c]);
            float sm = 0.f;
            for (int c = 0; c < NCLS; c++) sm += expf(lg[c] - mx);
            float lse = mx + logf(sm);
            for (int c = 0; c < NCLS; c++) out[g*NCLS + c] = lg[c] - lse;
        }
    }
    // reset bitmap for next invocation (all reads of bm finished at S5)
    for (int wdx = gtid; wdx < NN1*8; wdx += NT) bm[wdx] = 0u;
}

// ---------------- host launcher ----------------
extern "C" void kernel_launch(void* const* d_in, const int* in_sizes, int n_in,
                              void* d_out, int out_size){
    const float* x    = (const float*)d_in[0];
    const int*   ei   = (const int*)  d_in[1];
    const float* W1   = (const float*)d_in[2];
    const float* b1   = (const float*)d_in[3];
    const float* W2   = (const float*)d_in[4];
    const float* b2   = (const float*)d_in[5];
    const float* W3   = (const float*)d_in[6];
    const float* b3   = (const float*)d_in[7];
    const float* att1 = (const float*)d_in[8];
    const float* att2 = (const float*)d_in[9];
    const float* lw1  = (const float*)d_in[10];
    const float* lb1  = (const float*)d_in[11];
    const float* lw2  = (const float*)d_in[12];
    const float* lb2  = (const float*)d_in[13];
    const float* lw3  = (const float*)d_in[14];
    const float* lb3  = (const float*)d_in[15];
    float* out = (float*)d_out;
    int E = in_sizes[1]/2;

    k_all<<<NBLK, NTHR>>>(x, ei, E, W1, b1, W2, b2, W3, b3, att1, att2,
                          lw1, lb1, lw2, lb2, lw3, lb3, out);
}

// round 14
// speedup vs baseline: 1.0042x; 1.0042x over previous
#include <cuda_runtime.h>
#include <math.h>

#define NB     32
#define NPG1   256
#define NFEATD 128
#define NHID   64
#define KP1    128
#define KP2    64
#define NN1    (NB*NPG1)   // 8192
#define NN2    (NB*KP1)    // 4096
#define NN3    (NB*KP2)    // 2048
#define NCLS   6
#define PROJ_MAX 0.996f
#define MINN   1e-15f
#define AART   3.1063030f   // artanh(0.996)

// ---------------- device scratch ----------------
__device__ unsigned g_bm[NN1*8];        // layer-1 adjacency bitmap (256 bits/row)
__device__ float g_s[NN1];
__device__ float g_u[NN1*NHID];
__device__ float g_t1[NN1*NHID];
__device__ float g_dis[NN1];
__device__ float g_score[NN1];
__device__ int   g_lidx[NB*KP1];
__device__ float g_a1[NB*KP1];
__device__ float g_a2[NB*KP1];
__device__ float g_xn1[NN2*NHID];
__device__ float g_adj2[NB*KP1*KP1];
__device__ float g_t2[NN2*NHID];
__device__ float g_xn2[NN3*NHID];
__device__ float g_adj3[NB*KP2*KP2];
__device__ float g_t3[NN3*NHID];

// ---------------- helpers ----------------
__device__ __forceinline__ float artanh_(float x){
    x = fminf(fmaxf(x, -1.0f + 1e-7f), 1.0f - 1e-7f);
    return 0.5f*(log1pf(x) - log1pf(-x));
}
__device__ __forceinline__ float warpSum(float v){
    #pragma unroll
    for (int o = 16; o; o >>= 1) v += __shfl_xor_sync(0xffffffffu, v, o);
    return v;
}

__device__ __forceinline__ void hyp_tail(float mx0, float mx1, float xn,
                                         const float* __restrict__ bb, int l,
                                         float* __restrict__ up){
    float mxn = fmaxf(sqrtf(warpSum(mx0*mx0 + mx1*mx1)), MINN);
    float tv  = tanhf(mxn/xn*artanh_(xn));
    float hs  = tv/mxn;
    float h0 = mx0*hs, h1 = mx1*hs;
    float hn = tv;
    if (hn > PROJ_MAX){ float c = PROJ_MAX/hn; h0 *= c; h1 *= c; hn = PROJ_MAX; }
    float x2 = hn*hn;
    float b0 = bb[l], b1 = bb[l+32];
    float bn = fmaxf(sqrtf(warpSum(b0*b0 + b1*b1)), MINN);
    float tb = tanhf(bn);
    float hbs = tb/bn, hbn = tb;
    if (tb > PROJ_MAX){ hbs = PROJ_MAX/bn; hbn = PROJ_MAX; }
    float hb0 = b0*hbs, hb1 = b1*hbs;
    float y2 = hbn*hbn;
    float xy = warpSum(h0*hb0 + h1*hb1);
    float ca = 1.f + 2.f*xy + y2, cb = 1.f - x2;
    float den = fmaxf(1.f + 2.f*xy + x2*y2, MINN);
    float r0 = (ca*h0 + cb*hb0)/den, r1 = (ca*h1 + cb*hb1)/den;
    float rn = fmaxf(sqrtf(warpSum(r0*r0 + r1*r1)), MINN);
    float pn = rn, psc = 1.f;
    if (rn > PROJ_MAX){ psc = PROJ_MAX/rn; pn = PROJ_MAX; }
    float ls = artanh_(pn)/pn*psc;
    up[l] = r0*ls; up[l+32] = r1*ls;
}

__device__ __forceinline__ void agg_epi(int node, float a0, float a1, float deg,
                                        float* __restrict__ tout, float* __restrict__ dis, int l){
    float n1 = sqrtf(warpSum(a0*a0 + a1*a1));
    float s1 = (n1 > AART) ? AART/n1 : 1.f;
    float w0 = fmaxf(a0*s1, 0.f), w1 = fmaxf(a1*s1, 0.f);
    float n2 = sqrtf(warpSum(w0*w0 + w1*w1));
    float s2 = (n2 > AART) ? AART/n2 : 1.f;
    tout[(size_t)node*64 + l]      = w0*s2;
    tout[(size_t)node*64 + l + 32] = w1*s2;
    if (l == 0) dis[node] = (deg > 0.f) ? rsqrtf(deg) : 0.f;
}

// extract neighbor list of one 256-bit bitmap row into nbr[], returns count
__device__ __forceinline__ int extract_nbrs(const unsigned* __restrict__ bm, size_t idx,
                                            int* nbr){
    unsigned wd[8];
    #pragma unroll
    for (int i = 0; i < 8; i++) wd[i] = bm[idx + i];   // 8 loads issued up front
    int cnt = 0;
    #pragma unroll
    for (int i = 0; i < 8; i++){
        unsigned bits = wd[i];
        while (bits){
            int b = __ffs(bits) - 1; bits &= bits - 1;
            nbr[cnt++] = (i << 5) | b;
        }
    }
    return cnt;
}

// ---------------- K1: zero bitmap + row sums + to_hyp + HypLinear (layer1) ----------------
__global__ void k_prep1(const float* __restrict__ x, const float* __restrict__ W1,
                        const float* __restrict__ bb, unsigned* __restrict__ bm,
                        float* __restrict__ s, float* __restrict__ u){
    __shared__ float Wt[128*64];
    int tid = threadIdx.x;
    if (tid < 64) bm[blockIdx.x*64 + tid] = 0u;   // 1024 blocks x 64 = 64K words
    for (int e = tid; e < 128*64; e += 256){
        int j = e >> 7, k = e & 127;
        Wt[k*64 + j] = W1[e];
    }
    __syncthreads();
    int w = tid >> 5, l = tid & 31;
    int node = blockIdx.x*8 + w;
    const float* xp = x + (size_t)node*128;
    float xq[4];
    #pragma unroll
    for (int q = 0; q < 4; q++) xq[q] = xp[l + 32*q];
    float ssum = warpSum(xq[0]+xq[1]+xq[2]+xq[3]);
    if (l == 0) s[node] = ssum;
    float n0 = fmaxf(sqrtf(warpSum(xq[0]*xq[0]+xq[1]*xq[1]+xq[2]*xq[2]+xq[3]*xq[3])), MINN);
    float th = tanhf(n0);
    float xsc, xn;
    if (th > PROJ_MAX){ xsc = PROJ_MAX/n0; xn = PROJ_MAX; } else { xsc = th/n0; xn = th; }
    xn = fmaxf(xn, MINN);
    #pragma unroll
    for (int q = 0; q < 4; q++) xq[q] *= xsc;
    float mx0 = 0.f, mx1 = 0.f;
    #pragma unroll
    for (int q = 0; q < 4; q++){
        float xv = xq[q];
        for (int kk = 0; kk < 32; kk++){
            float xk = __shfl_sync(0xffffffffu, xv, kk);
            int k = q*32 + kk;
            mx0 += xk*Wt[k*64 + l];
            mx1 += xk*Wt[k*64 + l + 32];
        }
    }
    hyp_tail(mx0, mx1, xn, bb, l, u + (size_t)node*64);
}

// ---------------- K2: edge scatter -> bitmap ----------------
__global__ void k_scatter(const int* __restrict__ ei, int E, unsigned* __restrict__ bm){
    int e = blockIdx.x*blockDim.x + threadIdx.x;
    if (e >= E) return;
    int r = ei[e], c = ei[E + e];
    int lc = c & 255;
    atomicOr(&bm[(size_t)r*8 + (lc >> 5)], 1u << (lc & 31));
}

// ---------------- K3: sparse layer-1 HypAgg (chunked gathers, MLP~12) ----------------
__global__ void k_agg1(const unsigned* __restrict__ bm, const float* __restrict__ s,
                       const float* __restrict__ u, float* __restrict__ tout,
                       float* __restrict__ dis){
    int w = threadIdx.x >> 5, l = threadIdx.x & 31;
    int node = blockIdx.x*8 + w;
    int g = node >> 8;
    const float* ug = u + ((size_t)(g << 8))*64;
    const float* sg = s + (g << 8);
    float sn = sg[node & 255];
    int nbr[48];
    int cnt = extract_nbrs(bm, (size_t)node*8, nbr);
    float a0 = 0.f, a1 = 0.f, deg = 0.f;
    int m = 0;
    for (; m + 4 <= cnt; m += 4){
        int c0 = nbr[m], c1 = nbr[m+1], c2 = nbr[m+2], c3 = nbr[m+3];
        float s0 = sg[c0], s1 = sg[c1], s2 = sg[c2], s3 = sg[c3];
        float u00 = ug[(size_t)c0*64 + l], u01 = ug[(size_t)c0*64 + l + 32];
        float u10 = ug[(size_t)c1*64 + l], u11 = ug[(size_t)c1*64 + l + 32];
        float u20 = ug[(size_t)c2*64 + l], u21 = ug[(size_t)c2*64 + l + 32];
        float u30 = ug[(size_t)c3*64 + l], u31 = ug[(size_t)c3*64 + l + 32];
        float w0 = 0.5f*(sn + s0), w1 = 0.5f*(sn + s1);
        float w2 = 0.5f*(sn + s2), w3 = 0.5f*(sn + s3);
        a0 += w0*u00; a1 += w0*u01; deg += w0;
        a0 += w1*u10; a1 += w1*u11; deg += w1;
        a0 += w2*u20; a1 += w2*u21; deg += w2;
        a0 += w3*u30; a1 += w3*u31; deg += w3;
    }
    for (; m < cnt; m++){
        int c = nbr[m];
        float wv = 0.5f*(sn + sg[c]);
        a0 += wv*ug[(size_t)c*64 + l];
        a1 += wv*ug[(size_t)c*64 + l + 32];
        deg += wv;
    }
    agg_epi(node, a0, a1, deg, tout, dis, l);
}

// ---------------- K4: sparse layer-1 node information score (chunked) ----------------
__global__ void k_score1(const unsigned* __restrict__ bm, const float* __restrict__ s,
                         const float* __restrict__ t, const float* __restrict__ dis,
                         float* __restrict__ score){
    int w = threadIdx.x >> 5, l = threadIdx.x & 31;
    int node = blockIdx.x*8 + w;
    int g = node >> 8;
    const float* tg = t + ((size_t)(g << 8))*64;
    const float* sg = s + (g << 8);
    const float* dg = dis + (g << 8);
    float sn = sg[node & 255];
    float dn = dg[node & 255];
    int nbr[48];
    int cnt = extract_nbrs(bm, (size_t)node*8, nbr);
    float a0 = 0.f, a1 = 0.f;
    int m = 0;
    for (; m + 4 <= cnt; m += 4){
        int c0 = nbr[m], c1 = nbr[m+1], c2 = nbr[m+2], c3 = nbr[m+3];
        float s0 = sg[c0], s1 = sg[c1], s2 = sg[c2], s3 = sg[c3];
        float d0 = dg[c0], d1 = dg[c1], d2 = dg[c2], d3 = dg[c3];
        float u00 = tg[(size_t)c0*64 + l], u01 = tg[(size_t)c0*64 + l + 32];
        float u10 = tg[(size_t)c1*64 + l], u11 = tg[(size_t)c1*64 + l + 32];
        float u20 = tg[(size_t)c2*64 + l], u21 = tg[(size_t)c2*64 + l + 32];
        float u30 = tg[(size_t)c3*64 + l], u31 = tg[(size_t)c3*64 + l + 32];
        float w0 = 0.5f*(sn + s0)*d0, w1 = 0.5f*(sn + s1)*d1;
        float w2 = 0.5f*(sn + s2)*d2, w3 = 0.5f*(sn + s3)*d3;
        a0 += w0*u00; a1 += w0*u01;
        a0 += w1*u10; a1 += w1*u11;
        a0 += w2*u20; a1 += w2*u21;
        a0 += w3*u30; a1 += w3*u31;
    }
    for (; m < cnt; m++){
        int c = nbr[m];
        float wv = 0.5f*(sn + sg[c])*dg[c];
        a0 += wv*tg[(size_t)c*64 + l];
        a1 += wv*tg[(size_t)c*64 + l + 32];
    }
    float tr0 = tg[(size_t)(node & 255)*64 + l];
    float tr1 = tg[(size_t)(node & 255)*64 + l + 32];
    float d = fabsf(tr0 - dn*a0) + fabsf(tr1 - dn*a1);
    float sc = warpSum(d);
    if (l == 0) score[node] = sc;
}

// ---------------- K5: rank-based top-k selection ----------------
template<int NPG, int K>
__global__ void k_sel(const float* __restrict__ score, const float* __restrict__ tin,
                      const float* __restrict__ att, int* __restrict__ lidx,
                      float* __restrict__ a1, float* __restrict__ a2,
                      float* __restrict__ xn){
    __shared__ float key[NPG];
    __shared__ float satt[128];
    int g = blockIdx.x, t = threadIdx.x;          // blockDim == NPG
    key[t] = score[g*NPG + t];
    if (t < 128) satt[t] = att[t];
    __syncthreads();
    float kt = key[t];
    int rank = 0;
    #pragma unroll 8
    for (int p = 0; p < NPG; p++){
        float kp = key[p];
        rank += (kp > kt || (kp == kt && p < t)) ? 1 : 0;
    }
    if (rank < K){
        lidx[g*K + rank] = t;
        float tv = tanhf(kt);
        const float* src = tin + ((size_t)g*NPG + t)*64;
        float* dst = xn + ((size_t)g*K + rank)*64;
        float d1 = 0.f, d2 = 0.f;
        #pragma unroll 8
        for (int j = 0; j < 64; j++){
            float v = src[j]*tv; dst[j] = v;
            d1 += v*satt[j]; d2 += v*satt[64 + j];
        }
        a1[g*K + rank] = d1; a2[g*K + rank] = d2;
    }
}

// ---------------- K6a: build adj2 from bitmap ----------------
__global__ void k_adjb1(const int* __restrict__ lidx, const float* __restrict__ a1,
                        const float* __restrict__ a2, const unsigned* __restrict__ bm,
                        const float* __restrict__ s, float* __restrict__ adj2){
    int bi = blockIdx.x;             // g*128 + i
    int g = bi >> 7;
    int j = threadIdx.x;             // 128
    int li = lidx[bi];
    float a1i = a1[bi];
    int lj = lidx[(g << 7) + j];
    float ev = fmaxf(a1i + a2[(g << 7) + j], 0.f);
    unsigned word = bm[((size_t)(g << 8) + li)*8 + (lj >> 5)];
    float old = ((word >> (lj & 31)) & 1u) ? 0.5f*(s[(g << 8) + li] + s[(g << 8) + lj]) : 0.f;
    adj2[(size_t)bi*128 + j] = ev + old;
}

// ---------------- K6b: build adj3 from dense adj2 ----------------
__global__ void k_adjb2(const int* __restrict__ lidx, const float* __restrict__ a1,
                        const float* __restrict__ a2, const float* __restrict__ oldadj,
                        float* __restrict__ adj3){
    int bi = blockIdx.x;             // g*64 + i
    int g = bi >> 6;
    int j = threadIdx.x;             // 64
    int li = lidx[bi];
    float a1i = a1[bi];
    int lj = lidx[(g << 6) + j];
    float ev = fmaxf(a1i + a2[(g << 6) + j], 0.f);
    float old = oldadj[((size_t)(g << 7) + li)*128 + lj];
    adj3[(size_t)bi*64 + j] = ev + old;
}

// ---------------- K7: to_hyp + HypLinear, 64-dim ----------------
__global__ void k_linear(const float* __restrict__ xin, const float* __restrict__ W,
                         const float* __restrict__ bb, float* __restrict__ u){
    __shared__ float Wt[64*64];
    int tid = threadIdx.x;
    for (int e = tid; e < 4096; e += 256){
        int j = e >> 6, k = e & 63;
        Wt[k*64 + j] = W[e];
    }
    __syncthreads();
    int w = tid >> 5, l = tid & 31;
    int node = blockIdx.x*8 + w;
    const float* xp = xin + (size_t)node*64;
    float x0 = xp[l], x1 = xp[l+32];
    float n0 = fmaxf(sqrtf(warpSum(x0*x0 + x1*x1)), MINN);
    float th = tanhf(n0);
    float xsc, xn;
    if (th > PROJ_MAX){ xsc = PROJ_MAX/n0; xn = PROJ_MAX; } else { xsc = th/n0; xn = th; }
    xn = fmaxf(xn, MINN);
    x0 *= xsc; x1 *= xsc;
    float mx0 = 0.f, mx1 = 0.f;
    #pragma unroll
    for (int q = 0; q < 2; q++){
        float xv = q ? x1 : x0;
        for (int kk = 0; kk < 32; kk++){
            float xk = __shfl_sync(0xffffffffu, xv, kk);
            int k = q*32 + kk;
            mx0 += xk*Wt[k*64 + l];
            mx1 += xk*Wt[k*64 + l + 32];
        }
    }
    hyp_tail(mx0, mx1, xn, bb, l, u + (size_t)node*64);
}

// ---------------- dense HypAgg layer2: 4 rows/warp, 32-row tiles ----------------
__global__ void k_agg2(const float* __restrict__ adj, const float* __restrict__ u,
                       float* __restrict__ tout, float* __restrict__ dis){
    __shared__ float ush[KP1*64];
    int g = blockIdx.x >> 2, rt = blockIdx.x & 3;   // grid = NB*4 = 128
    int w = threadIdx.x >> 5, l = threadIdx.x & 31;
    int rbase = rt*32 + w*4;
    const float* adjg = adj + (size_t)g*KP1*KP1;
    const float* ug   = u   + (size_t)g*KP1*64;
    {
        const float4* src = (const float4*)ug;
        float4* dst = (float4*)ush;
        for (int e = threadIdx.x; e < KP1*16; e += 256) dst[e] = src[e];
    }
    __syncthreads();
    const float* rp0 = adjg + (size_t)(rbase+0)*KP1;
    const float* rp1 = adjg + (size_t)(rbase+1)*KP1;
    const float* rp2 = adjg + (size_t)(rbase+2)*KP1;
    const float* rp3 = adjg + (size_t)(rbase+3)*KP1;
    float acc[4][2] = {}; float dgv[4] = {};
    #pragma unroll 2
    for (int m = 0; m < KP1; m += 4){
        float4 v0 = *(const float4*)(rp0 + m);
        float4 v1 = *(const float4*)(rp1 + m);
        float4 v2 = *(const float4*)(rp2 + m);
        float4 v3 = *(const float4*)(rp3 + m);
        float ar[4][4] = {{v0.x,v0.y,v0.z,v0.w},{v1.x,v1.y,v1.z,v1.w},
                          {v2.x,v2.y,v2.z,v2.w},{v3.x,v3.y,v3.z,v3.w}};
        #pragma unroll
        for (int q = 0; q < 4; q++){
            float u0 = ush[(m+q)*64 + l];
            float u1 = ush[(m+q)*64 + l + 32];
            #pragma unroll
            for (int i = 0; i < 4; i++){
                acc[i][0] += ar[i][q]*u0; acc[i][1] += ar[i][q]*u1; dgv[i] += ar[i][q];
            }
        }
    }
    int nb = g*KP1 + rbase;
    #pragma unroll
    for (int i = 0; i < 4; i++)
        agg_epi(nb+i, acc[i][0], acc[i][1], dgv[i], tout, dis, l);
}

// ---------------- dense score layer2: 4 rows/warp ----------------
__global__ void k_sco2(const float* __restrict__ adj, const float* __restrict__ t,
                       const float* __restrict__ dis, float* __restrict__ score){
    __shared__ float tsh[KP1*64];
    int g = blockIdx.x >> 2, rt = blockIdx.x & 3;
    int w = threadIdx.x >> 5, l = threadIdx.x & 31;
    int rbase = rt*32 + w*4;
    const float* adjg = adj + (size_t)g*KP1*KP1;
    const float* tg   = t   + (size_t)g*KP1*64;
    const float* disg = dis + (size_t)g*KP1;
    {
        const float4* src = (const float4*)tg;
        float4* dst = (float4*)tsh;
        for (int e = threadIdx.x; e < KP1*16; e += 256){
            float4 v = src[e];
            float dm = disg[e >> 4];
            v.x *= dm; v.y *= dm; v.z *= dm; v.w *= dm;
            dst[e] = v;
        }
    }
    float tr[4][2], dr[4];
    #pragma unroll
    for (int i = 0; i < 4; i++){
        tr[i][0] = tg[(size_t)(rbase+i)*64 + l];
        tr[i][1] = tg[(size_t)(rbase+i)*64 + l + 32];
        dr[i]    = disg[rbase+i];
    }
    __syncthreads();
    const float* rp0 = adjg + (size_t)(rbase+0)*KP1;
    const float* rp1 = adjg + (size_t)(rbase+1)*KP1;
    const float* rp2 = adjg + (size_t)(rbase+2)*KP1;
    const float* rp3 = adjg + (size_t)(rbase+3)*KP1;
    float acc[4][2] = {};
    #pragma unroll 2
    for (int m = 0; m < KP1; m += 4){
        float4 v0 = *(const float4*)(rp0 + m);
        float4 v1 = *(const float4*)(rp1 + m);
        float4 v2 = *(const float4*)(rp2 + m);
        float4 v3 = *(const float4*)(rp3 + m);
        float ar[4][4] = {{v0.x,v0.y,v0.z,v0.w},{v1.x,v1.y,v1.z,v1.w},
                          {v2.x,v2.y,v2.z,v2.w},{v3.x,v3.y,v3.z,v3.w}};
        #pragma unroll
        for (int q = 0; q < 4; q++){
            float u0 = tsh[(m+q)*64 + l];
            float u1 = tsh[(m+q)*64 + l + 32];
            #pragma unroll
            for (int i = 0; i < 4; i++){
                acc[i][0] += ar[i][q]*u0; acc[i][1] += ar[i][q]*u1;
            }
        }
    }
    #pragma unroll
    for (int i = 0; i < 4; i++){
        float d = fabsf(tr[i][0] - dr[i]*acc[i][0]) + fabsf(tr[i][1] - dr[i]*acc[i][1]);
        float sc = warpSum(d);
        if (l == 0) score[g*KP1 + rbase + i] = sc;
    }
}

// ---------------- dense HypAgg layer3 (64): 2 rows/warp, 16-row tiles ----------------
__global__ void k_agg3(const float* __restrict__ adj, const float* __restrict__ u,
                       float* __restrict__ tout, float* __restrict__ dis){
    __shared__ float ush[KP2*64];
    int g = blockIdx.x >> 2, rt = blockIdx.x & 3;   // grid = NB*4 = 128
    int w = threadIdx.x >> 5, l = threadIdx.x & 31;
    int rbase = rt*16 + w*2;
    const float* adjg = adj + (size_t)g*KP2*KP2;
    const float* ug   = u   + (size_t)g*KP2*64;
    {
        const float4* src = (const float4*)ug;
        float4* dst = (float4*)ush;
        for (int e = threadIdx.x; e < KP2*16; e += 256) dst[e] = src[e];
    }
    __syncthreads();
    const float* r0p = adjg + (size_t)rbase*KP2;
    const float* r1p = r0p + KP2;
    float a00=0,a01=0,a10=0,a11=0,d0=0,d1=0;
    #pragma unroll 4
    for (int m = 0; m < KP2; m += 4){
        float4 v0 = *(const float4*)(r0p + m);
        float4 v1 = *(const float4*)(r1p + m);
        float ar0[4] = {v0.x, v0.y, v0.z, v0.w};
        float ar1[4] = {v1.x, v1.y, v1.z, v1.w};
        #pragma unroll
        for (int q = 0; q < 4; q++){
            float u0 = ush[(m+q)*64 + l];
            float u1 = ush[(m+q)*64 + l + 32];
            a00 += ar0[q]*u0; a01 += ar0[q]*u1; d0 += ar0[q];
            a10 += ar1[q]*u0; a11 += ar1[q]*u1; d1 += ar1[q];
        }
    }
    int nb = g*KP2 + rbase;
    agg_epi(nb,   a00, a01, d0, tout, dis, l);
    agg_epi(nb+1, a10, a11, d1, tout, dis, l);
}

// ---------------- K8: readouts + MLP head + log_softmax ----------------
__global__ void k_final(const float* __restrict__ xn1, const float* __restrict__ xn2,
                        const float* __restrict__ t3,
                        const float* __restrict__ lw1, const float* __restrict__ lb1,
                        const float* __restrict__ lw2, const float* __restrict__ lb2,
                        const float* __restrict__ lw3, const float* __restrict__ lb3,
                        float* __restrict__ out){
    __shared__ float sA[4*64], sB[4*64], rr[128], h1[64], h2[32], lg[NCLS];
    int g = blockIdx.x, t = threadIdx.x;
    int f = t & 63, grp = t >> 6;
    float accM = 0.f, accE = 0.f;
    #pragma unroll
    for (int srci = 0; srci < 3; srci++){
        const float* base = (srci == 0) ? xn1 + (size_t)g*KP1*64
                          : (srci == 1) ? xn2 + (size_t)g*KP2*64
                                        : t3  + (size_t)g*KP2*64;
        int K = (srci == 0) ? KP1 : KP2;
        float pm = -3.402823466e38f, ps = 0.f;
        for (int i = grp; i < K; i += 4){
            float v = base[(size_t)i*64 + f];
            pm = fmaxf(pm, v); ps += v;
        }
        sA[grp*64 + f] = pm; sB[grp*64 + f] = ps;
        __syncthreads();
        if (t < 64){
            float mx = fmaxf(fmaxf(sA[f], sA[64+f]), fmaxf(sA[128+f], sA[192+f]));
            float sm = sB[f] + sB[64+f] + sB[128+f] + sB[192+f];
            accM += fmaxf(mx, 0.f);
            accE += fmaxf(sm/(float)K, 0.f);
        }
        __syncthreads();
    }
    if (t < 64){ rr[f] = accM; rr[64+f] = accE; }
    __syncthreads();
    if (t < 64){
        float a = lb1[t];
        #pragma unroll 8
        for (int q = 0; q < 128; q++) a += lw1[(size_t)t*128 + q]*rr[q];
        h1[t] = fmaxf(a, 0.f);
    }
    __syncthreads();
    if (t < 32){
        float a = lb2[t];
        #pragma unroll 8
        for (int q = 0; q < 64; q++) a += lw2[(size_t)t*64 + q]*h1[q];
        h2[t] = fmaxf(a, 0.f);
    }
    __syncthreads();
    if (t < NCLS){
        float a = lb3[t];
        #pragma unroll
        for (int q = 0; q < 32; q++) a += lw3[(size_t)t*32 + q]*h2[q];
        lg[t] = a;
    }
    __syncthreads();
    if (t == 0){
        float mx = lg[0];
        for (int c = 1; c < NCLS; c++) mx = fmaxf(mx, lg[c]);
        float sm = 0.f;
        for (int c = 0; c < NCLS; c++) sm += expf(lg[c] - mx);
        float lse = mx + logf(sm);
        for (int c = 0; c < NCLS; c++) out[g*NCLS + c] = lg[c] - lse;
    }
}

// ---------------- host launcher ----------------
extern "C" void kernel_launch(void* const* d_in, const int* in_sizes, int n_in,
                              void* d_out, int out_size){
    const float* x    = (const float*)d_in[0];
    const int*   ei   = (const int*)  d_in[1];
    const float* W1   = (const float*)d_in[2];
    const float* b1   = (const float*)d_in[3];
    const float* W2   = (const float*)d_in[4];
    const float* b2   = (const float*)d_in[5];
    const float* W3   = (const float*)d_in[6];
    const float* b3   = (const float*)d_in[7];
    const float* att1 = (const float*)d_in[8];
    const float* att2 = (const float*)d_in[9];
    const float* lw1  = (const float*)d_in[10];
    const float* lb1  = (const float*)d_in[11];
    const float* lw2  = (const float*)d_in[12];
    const float* lb2  = (const float*)d_in[13];
    const float* lw3  = (const float*)d_in[14];
    const float* lb3  = (const float*)d_in[15];
    float* out = (float*)d_out;
    int E = in_sizes[1]/2;

    unsigned* bm; int* lidx;
    float *s, *u, *t1, *dis, *score, *a1, *a2, *xn1, *adj2, *t2, *xn2, *adj3, *t3;
    cudaGetSymbolAddress((void**)&bm,    g_bm);
    cudaGetSymbolAddress((void**)&s,     g_s);
    cudaGetSymbolAddress((void**)&u,     g_u);
    cudaGetSymbolAddress((void**)&t1,    g_t1);
    cudaGetSymbolAddress((void**)&dis,   g_dis);
    cudaGetSymbolAddress((void**)&score, g_score);
    cudaGetSymbolAddress((void**)&lidx,  g_lidx);
    cudaGetSymbolAddress((void**)&a1,    g_a1);
    cudaGetSymbolAddress((void**)&a2,    g_a2);
    cudaGetSymbolAddress((void**)&xn1,   g_xn1);
    cudaGetSymbolAddress((void**)&adj2,  g_adj2);
    cudaGetSymbolAddress((void**)&t2,    g_t2);
    cudaGetSymbolAddress((void**)&xn2,   g_xn2);
    cudaGetSymbolAddress((void**)&adj3,  g_adj3);
    cudaGetSymbolAddress((void**)&t3,    g_t3);

    // layer 1 (sparse bitmap)
    k_prep1   <<<NN1/8, 256>>>(x, W1, b1, bm, s, u);
    k_scatter <<<(E + 255)/256, 256>>>(ei, E, bm);
    k_agg1    <<<NN1/8, 256>>>(bm, s, u, t1, dis);
    k_score1  <<<NN1/8, 256>>>(bm, s, t1, dis, score);
    k_sel<NPG1,KP1><<<NB, NPG1>>>(score, t1, att1, lidx, a1, a2, xn1);
    k_adjb1   <<<NB*KP1, KP1>>>(lidx, a1, a2, bm, s, adj2);
    // layer 2 (dense 128, 4 rows/warp)
    k_linear  <<<NN2/8, 256>>>(xn1, W2, b2, u);
    k_agg2    <<<NB*4, 256>>>(adj2, u, t2, dis);
    k_sco2    <<<NB*4, 256>>>(adj2, t2, dis, score);
    k_sel<KP1,KP2><<<NB, KP1>>>(score, t2, att2, lidx, a1, a2, xn2);
    k_adjb2   <<<NB*KP2, KP2>>>(lidx, a1, a2, adj2, adj3);
    // layer 3 (dense 64)
    k_linear  <<<NN3/8, 256>>>(xn2, W3, b3, u);
    k_agg3    <<<NB*4, 256>>>(adj3, u, t3, dis);
    // readout + MLP
    k_final   <<<NB, 256>>>(xn1, xn2, t3, lw1, lb1, lw2, lb2, lw3, lb3, out);
}

// round 16
// speedup vs baseline: 1.0262x; 1.0219x over previous
#include <cuda_runtime.h>
#include <math.h>

#define NB     32
#define NPG1   256
#define NFEATD 128
#define NHID   64
#define KP1    128
#define KP2    64
#define NN1    (NB*NPG1)   // 8192
#define NN2    (NB*KP1)    // 4096
#define NN3    (NB*KP2)    // 2048
#define NCLS   6
#define PROJ_MAX 0.996f
#define MINN   1e-15f
#define AART   3.1063030f   // artanh(0.996)

// ---------------- device scratch ----------------
__device__ unsigned g_bm[NN1*8];        // layer-1 bitmap; ALWAYS zero at kernel_launch entry
__device__ float g_s[NN1];
__device__ float g_u[NN1*NHID];
__device__ float g_t1[NN1*NHID];
__device__ float g_dis[NN1];
__device__ float g_score[NN1];
__device__ int   g_lidx[NB*KP1];
__device__ float g_a1[NB*KP1];
__device__ float g_a2[NB*KP1];
__device__ float g_xn1[NN2*NHID];
__device__ float g_adj2[NB*KP1*KP1];
__device__ float g_t2[NN2*NHID];
__device__ float g_xn2[NN3*NHID];
__device__ float g_adj3[NB*KP2*KP2];
__device__ float g_t3[NN3*NHID];

// ---------------- helpers ----------------
__device__ __forceinline__ float artanh_(float x){
    x = fminf(fmaxf(x, -1.0f + 1e-7f), 1.0f - 1e-7f);
    return 0.5f*(log1pf(x) - log1pf(-x));
}
__device__ __forceinline__ float warpSum(float v){
    #pragma unroll
    for (int o = 16; o; o >>= 1) v += __shfl_xor_sync(0xffffffffu, v, o);
    return v;
}

__device__ __forceinline__ void hyp_tail(float mx0, float mx1, float xn,
                                         const float* __restrict__ bb, int l,
                                         float* __restrict__ up){
    float mxn = fmaxf(sqrtf(warpSum(mx0*mx0 + mx1*mx1)), MINN);
    float tv  = tanhf(mxn/xn*artanh_(xn));
    float hs  = tv/mxn;
    float h0 = mx0*hs, h1 = mx1*hs;
    float hn = tv;
    if (hn > PROJ_MAX){ float c = PROJ_MAX/hn; h0 *= c; h1 *= c; hn = PROJ_MAX; }
    float x2 = hn*hn;
    float b0 = bb[l], b1 = bb[l+32];
    float bn = fmaxf(sqrtf(warpSum(b0*b0 + b1*b1)), MINN);
    float tb = tanhf(bn);
    float hbs = tb/bn, hbn = tb;
    if (tb > PROJ_MAX){ hbs = PROJ_MAX/bn; hbn = PROJ_MAX; }
    float hb0 = b0*hbs, hb1 = b1*hbs;
    float y2 = hbn*hbn;
    float xy = warpSum(h0*hb0 + h1*hb1);
    float ca = 1.f + 2.f*xy + y2, cb = 1.f - x2;
    float den = fmaxf(1.f + 2.f*xy + x2*y2, MINN);
    float r0 = (ca*h0 + cb*hb0)/den, r1 = (ca*h1 + cb*hb1)/den;
    float rn = fmaxf(sqrtf(warpSum(r0*r0 + r1*r1)), MINN);
    float pn = rn, psc = 1.f;
    if (rn > PROJ_MAX){ psc = PROJ_MAX/rn; pn = PROJ_MAX; }
    float ls = artanh_(pn)/pn*psc;
    up[l] = r0*ls; up[l+32] = r1*ls;
}

__device__ __forceinline__ void agg_epi(int node, float a0, float a1, float deg,
                                        float* __restrict__ tout, float* __restrict__ dis, int l){
    float n1 = sqrtf(warpSum(a0*a0 + a1*a1));
    float s1 = (n1 > AART) ? AART/n1 : 1.f;
    float w0 = fmaxf(a0*s1, 0.f), w1 = fmaxf(a1*s1, 0.f);
    float n2 = sqrtf(warpSum(w0*w0 + w1*w1));
    float s2 = (n2 > AART) ? AART/n2 : 1.f;
    tout[(size_t)node*64 + l]      = w0*s2;
    tout[(size_t)node*64 + l + 32] = w1*s2;
    if (l == 0) dis[node] = (deg > 0.f) ? rsqrtf(deg) : 0.f;
}

// ---------------- K1: edge scatter (bm pre-zeroed invariant) + row sums + to_hyp + HypLinear ----------------
__global__ void k_prep1(const float* __restrict__ x, const float* __restrict__ W1,
                        const float* __restrict__ bb, const int* __restrict__ ei, int E,
                        unsigned* __restrict__ bm, float* __restrict__ s, float* __restrict__ u){
    __shared__ float Wt[128*64];
    int tid = threadIdx.x;
    // scatter: 1024 blocks x 256 = 262144 threads >= E
    for (int e = blockIdx.x*256 + tid; e < E; e += 1024*256){
        int r = ei[e], c = ei[E + e];
        int lc = c & 255;
        atomicOr(&bm[(size_t)r*8 + (lc >> 5)], 1u << (lc & 31));
    }
    for (int e = tid; e < 128*64; e += 256){
        int j = e >> 7, k = e & 127;
        Wt[k*64 + j] = W1[e];
    }
    __syncthreads();
    int w = tid >> 5, l = tid & 31;
    int node = blockIdx.x*8 + w;
    const float* xp = x + (size_t)node*128;
    float xq[4];
    #pragma unroll
    for (int q = 0; q < 4; q++) xq[q] = xp[l + 32*q];
    float ssum = warpSum(xq[0]+xq[1]+xq[2]+xq[3]);
    if (l == 0) s[node] = ssum;
    float n0 = fmaxf(sqrtf(warpSum(xq[0]*xq[0]+xq[1]*xq[1]+xq[2]*xq[2]+xq[3]*xq[3])), MINN);
    float th = tanhf(n0);
    float xsc, xn;
    if (th > PROJ_MAX){ xsc = PROJ_MAX/n0; xn = PROJ_MAX; } else { xsc = th/n0; xn = th; }
    xn = fmaxf(xn, MINN);
    #pragma unroll
    for (int q = 0; q < 4; q++) xq[q] *= xsc;
    float mx0 = 0.f, mx1 = 0.f;
    #pragma unroll
    for (int q = 0; q < 4; q++){
        float xv = xq[q];
        for (int kk = 0; kk < 32; kk++){
            float xk = __shfl_sync(0xffffffffu, xv, kk);
            int k = q*32 + kk;
            mx0 += xk*Wt[k*64 + l];
            mx1 += xk*Wt[k*64 + l + 32];
        }
    }
    hyp_tail(mx0, mx1, xn, bb, l, u + (size_t)node*64);
}

// ---------------- K3: sparse layer-1 HypAgg, 4 sub-warps per node ----------------
// Each sub-warp scans 2 of the 8 bitmap words (~4 nbrs): serial gather chain /4.
__global__ void k_agg1(const unsigned* __restrict__ bm, const float* __restrict__ s,
                       const float* __restrict__ u, float* __restrict__ tout,
                       float* __restrict__ dis){
    __shared__ float sP0[2][4][32];
    __shared__ float sP1[2][4][32];
    __shared__ float sDg[2][4];
    int tid = threadIdx.x;
    int nib = tid >> 7;          // node in block (0..1)
    int sw  = (tid >> 5) & 3;    // sub-warp (0..3)
    int l   = tid & 31;
    int node = blockIdx.x*2 + nib;
    int g = node >> 8;
    const float* ug = u + ((size_t)(g << 8))*64;
    const float* sg = s + (g << 8);
    float sn = sg[node & 255];
    float a0 = 0.f, a1 = 0.f, deg = 0.f;
    #pragma unroll
    for (int wi = 0; wi < 2; wi++){
        int w8 = sw*2 + wi;
        unsigned bits = bm[(size_t)node*8 + w8];
        int base = w8 << 5;
        while (bits){
            int b = __ffs(bits) - 1; bits &= bits - 1;
            int c = base | b;
            float wv = 0.5f*(sn + sg[c]);
            a0 += wv*ug[(size_t)c*64 + l];
            a1 += wv*ug[(size_t)c*64 + l + 32];
            deg += wv;
        }
    }
    sP0[nib][sw][l] = a0;
    sP1[nib][sw][l] = a1;
    if (l == 0) sDg[nib][sw] = deg;   // deg lane-invariant
    __syncthreads();
    if (sw == 0){
        float A0 = sP0[nib][0][l] + sP0[nib][1][l] + sP0[nib][2][l] + sP0[nib][3][l];
        float A1 = sP1[nib][0][l] + sP1[nib][1][l] + sP1[nib][2][l] + sP1[nib][3][l];
        float DG = sDg[nib][0] + sDg[nib][1] + sDg[nib][2] + sDg[nib][3];
        agg_epi(node, A0, A1, DG, tout, dis, l);
    }
}

// ---------------- K4: sparse layer-1 node information score, 4 sub-warps per node ----------------
__global__ void k_score1(const unsigned* __restrict__ bm, const float* __restrict__ s,
                         const float* __restrict__ t, const float* __restrict__ dis,
                         float* __restrict__ score){
    __shared__ float sP0[2][4][32];
    __shared__ float sP1[2][4][32];
    int tid = threadIdx.x;
    int nib = tid >> 7;
    int sw  = (tid >> 5) & 3;
    int l   = tid & 31;
    int node = blockIdx.x*2 + nib;
    int g = node >> 8;
    const float* tg = t + ((size_t)(g << 8))*64;
    const float* sg = s + (g << 8);
    const float* dg = dis + (g << 8);
    float sn = sg[node & 255];
    float a0 = 0.f, a1 = 0.f;
    #pragma unroll
    for (int wi = 0; wi < 2; wi++){
        int w8 = sw*2 + wi;
        unsigned bits = bm[(size_t)node*8 + w8];
        int base = w8 << 5;
        while (bits){
            int b = __ffs(bits) - 1; bits &= bits - 1;
            int c = base | b;
            float wv = 0.5f*(sn + sg[c])*dg[c];
            a0 += wv*tg[(size_t)c*64 + l];
            a1 += wv*tg[(size_t)c*64 + l + 32];
        }
    }
    sP0[nib][sw][l] = a0;
    sP1[nib][sw][l] = a1;
    __syncthreads();
    if (sw == 0){
        float A0 = sP0[nib][0][l] + sP0[nib][1][l] + sP0[nib][2][l] + sP0[nib][3][l];
        float A1 = sP1[nib][0][l] + sP1[nib][1][l] + sP1[nib][2][l] + sP1[nib][3][l];
        float dn = dg[node & 255];
        float tr0 = tg[(size_t)(node & 255)*64 + l];
        float tr1 = tg[(size_t)(node & 255)*64 + l + 32];
        float d = fabsf(tr0 - dn*A0) + fabsf(tr1 - dn*A1);
        float sc = warpSum(d);
        if (l == 0) score[node] = sc;
    }
}

// ---------------- K5: rank-based top-k selection ----------------
template<int NPG, int K>
__global__ void k_sel(const float* __restrict__ score, const float* __restrict__ tin,
                      const float* __restrict__ att, int* __restrict__ lidx,
                      float* __restrict__ a1, float* __restrict__ a2,
                      float* __restrict__ xn){
    __shared__ float key[NPG];
    __shared__ float satt[128];
    int g = blockIdx.x, t = threadIdx.x;          // blockDim == NPG
    key[t] = score[g*NPG + t];
    if (t < 128) satt[t] = att[t];
    __syncthreads();
    float kt = key[t];
    int rank = 0;
    #pragma unroll 8
    for (int p = 0; p < NPG; p++){
        float kp = key[p];
        rank += (kp > kt || (kp == kt && p < t)) ? 1 : 0;
    }
    if (rank < K){
        lidx[g*K + rank] = t;
        float tv = tanhf(kt);
        const float* src = tin + ((size_t)g*NPG + t)*64;
        float* dst = xn + ((size_t)g*K + rank)*64;
        float d1 = 0.f, d2 = 0.f;
        #pragma unroll 8
        for (int j = 0; j < 64; j++){
            float v = src[j]*tv; dst[j] = v;
            d1 += v*satt[j]; d2 += v*satt[64 + j];
        }
        a1[g*K + rank] = d1; a2[g*K + rank] = d2;
    }
}

// ---------------- K6a: build adj2 from bitmap ----------------
__global__ void k_adjb1(const int* __restrict__ lidx, const float* __restrict__ a1,
                        const float* __restrict__ a2, const unsigned* __restrict__ bm,
                        const float* __restrict__ s, float* __restrict__ adj2){
    int bi = blockIdx.x;             // g*128 + i
    int g = bi >> 7;
    int j = threadIdx.x;             // 128
    int li = lidx[bi];
    float a1i = a1[bi];
    int lj = lidx[(g << 7) + j];
    float ev = fmaxf(a1i + a2[(g << 7) + j], 0.f);
    unsigned word = bm[((size_t)(g << 8) + li)*8 + (lj >> 5)];
    float old = ((word >> (lj & 31)) & 1u) ? 0.5f*(s[(g << 8) + li] + s[(g << 8) + lj]) : 0.f;
    adj2[(size_t)bi*128 + j] = ev + old;
}

// ---------------- K6b: build adj3 from dense adj2 ----------------
__global__ void k_adjb2(const int* __restrict__ lidx, const float* __restrict__ a1,
                        const float* __restrict__ a2, const float* __restrict__ oldadj,
                        float* __restrict__ adj3){
    int bi = blockIdx.x;             // g*64 + i
    int g = bi >> 6;
    int j = threadIdx.x;             // 64
    int li = lidx[bi];
    float a1i = a1[bi];
    int lj = lidx[(g << 6) + j];
    float ev = fmaxf(a1i + a2[(g << 6) + j], 0.f);
    float old = oldadj[((size_t)(g << 7) + li)*128 + lj];
    adj3[(size_t)bi*64 + j] = ev + old;
}

// ---------------- K7: to_hyp + HypLinear, 64-dim (+optional bitmap re-zero) ----------------
__global__ void k_linear(const float* __restrict__ xin, const float* __restrict__ W,
                         const float* __restrict__ bb, float* __restrict__ u,
                         unsigned* __restrict__ bmz){
    __shared__ float Wt[64*64];
    int tid = threadIdx.x;
    if (bmz){   // restore bm==0 invariant (all bm readers are upstream in stream order)
        int gt = blockIdx.x*256 + tid;
        if (gt < NN1*8) bmz[gt] = 0u;
    }
    for (int e = tid; e < 4096; e += 256){
        int j = e >> 6, k = e & 63;
        Wt[k*64 + j] = W[e];
    }
    __syncthreads();
    int w = tid >> 5, l = tid & 31;
    int node = blockIdx.x*8 + w;
    const float* xp = xin + (size_t)node*64;
    float x0 = xp[l], x1 = xp[l+32];
    float n0 = fmaxf(sqrtf(warpSum(x0*x0 + x1*x1)), MINN);
    float th = tanhf(n0);
    float xsc, xn;
    if (th > PROJ_MAX){ xsc = PROJ_MAX/n0; xn = PROJ_MAX; } else { xsc = th/n0; xn = th; }
    xn = fmaxf(xn, MINN);
    x0 *= xsc; x1 *= xsc;
    float mx0 = 0.f, mx1 = 0.f;
    #pragma unroll
    for (int q = 0; q < 2; q++){
        float xv = q ? x1 : x0;
        for (int kk = 0; kk < 32; kk++){
            float xk = __shfl_sync(0xffffffffu, xv, kk);
            int k = q*32 + kk;
            mx0 += xk*Wt[k*64 + l];
            mx1 += xk*Wt[k*64 + l + 32];
        }
    }
    hyp_tail(mx0, mx1, xn, bb, l, u + (size_t)node*64);
}

// ---------------- dense HypAgg, 2 rows/warp (measured-best R10 form) ----------------
template<int NPG>
__global__ void k_aggT(const float* __restrict__ adj, const float* __restrict__ u,
                       float* __restrict__ tout, float* __restrict__ dis){
    constexpr int TPG = NPG/16;
    __shared__ float ush[NPG*64];
    int g = blockIdx.x / TPG, rt = blockIdx.x % TPG;
    int w = threadIdx.x >> 5, l = threadIdx.x & 31;
    int rbase = rt*16 + w*2;
    const float* adjg = adj + (size_t)g*NPG*NPG;
    const float* ug   = u   + (size_t)g*NPG*64;
    {
        const float4* src = (const float4*)ug;
        float4* dst = (float4*)ush;
        for (int e = threadIdx.x; e < NPG*16; e += 256) dst[e] = src[e];
    }
    __syncthreads();
    const float* r0p = adjg + (size_t)rbase*NPG;
    const float* r1p = r0p + NPG;
    float a00=0,a01=0,a10=0,a11=0,d0=0,d1=0;
    #pragma unroll 4
    for (int m = 0; m < NPG; m += 4){
        float4 v0 = *(const float4*)(r0p + m);
        float4 v1 = *(const float4*)(r1p + m);
        float ar0[4] = {v0.x, v0.y, v0.z, v0.w};
        float ar1[4] = {v1.x, v1.y, v1.z, v1.w};
        #pragma unroll
        for (int q = 0; q < 4; q++){
            float u0 = ush[(m+q)*64 + l];
            float u1 = ush[(m+q)*64 + l + 32];
            a00 += ar0[q]*u0; a01 += ar0[q]*u1; d0 += ar0[q];
            a10 += ar1[q]*u0; a11 += ar1[q]*u1; d1 += ar1[q];
        }
    }
    int nb = g*NPG + rbase;
    agg_epi(nb,   a00, a01, d0, tout, dis, l);
    agg_epi(nb+1, a10, a11, d1, tout, dis, l);
}

// ---------------- dense node information score, 2 rows/warp ----------------
template<int NPG>
__global__ void k_scoreT(const float* __restrict__ adj, const float* __restrict__ t,
                         const float* __restrict__ dis, float* __restrict__ score){
    constexpr int TPG = NPG/16;
    __shared__ float tsh[NPG*64];
    int g = blockIdx.x / TPG, rt = blockIdx.x % TPG;
    int w = threadIdx.x >> 5, l = threadIdx.x & 31;
    int rbase = rt*16 + w*2;
    const float* adjg = adj + (size_t)g*NPG*NPG;
    const float* tg   = t   + (size_t)g*NPG*64;
    const float* disg = dis + (size_t)g*NPG;
    {
        const float4* src = (const float4*)tg;
        float4* dst = (float4*)tsh;
        for (int e = threadIdx.x; e < NPG*16; e += 256){
            float4 v = src[e];
            float dm = disg[e >> 4];
            v.x *= dm; v.y *= dm; v.z *= dm; v.w *= dm;
            dst[e] = v;
        }
    }
    float tr0 = tg[(size_t)rbase*64 + l],     tr1 = tg[(size_t)rbase*64 + l + 32];
    float sr0 = tg[(size_t)(rbase+1)*64 + l], sr1 = tg[(size_t)(rbase+1)*64 + l + 32];
    float dr0 = disg[rbase], dr1 = disg[rbase+1];
    __syncthreads();
    const float* r0p = adjg + (size_t)rbase*NPG;
    const float* r1p = r0p + NPG;
    float a00=0,a01=0,a10=0,a11=0;
    #pragma unroll 4
    for (int m = 0; m < NPG; m += 4){
        float4 v0 = *(const float4*)(r0p + m);
        float4 v1 = *(const float4*)(r1p + m);
        float ar0[4] = {v0.x, v0.y, v0.z, v0.w};
        float ar1[4] = {v1.x, v1.y, v1.z, v1.w};
        #pragma unroll
        for (int q = 0; q < 4; q++){
            float u0 = tsh[(m+q)*64 + l];
            float u1 = tsh[(m+q)*64 + l + 32];
            a00 += ar0[q]*u0; a01 += ar0[q]*u1;
            a10 += ar1[q]*u0; a11 += ar1[q]*u1;
        }
    }
    float d0 = fabsf(tr0 - dr0*a00) + fabsf(tr1 - dr0*a01);
    float d1 = fabsf(sr0 - dr1*a10) + fabsf(sr1 - dr1*a11);
    float sc0 = warpSum(d0), sc1 = warpSum(d1);
    if (l == 0){ score[g*NPG + rbase] = sc0; score[g*NPG + rbase + 1] = sc1; }
}

// ---------------- K8: readouts + MLP head + log_softmax ----------------
__global__ void k_final(const float* __restrict__ xn1, const float* __restrict__ xn2,
                        const float* __restrict__ t3,
                        const float* __restrict__ lw1, const float* __restrict__ lb1,
                        const float* __restrict__ lw2, const float* __restrict__ lb2,
                        const float* __restrict__ lw3, const float* __restrict__ lb3,
                        float* __restrict__ out){
    __shared__ float sA[4*64], sB[4*64], rr[128], h1[64], h2[32], lg[NCLS];
    int g = blockIdx.x, t = threadIdx.x;
    int f = t & 63, grp = t >> 6;
    float accM = 0.f, accE = 0.f;
    #pragma unroll
    for (int srci = 0; srci < 3; srci++){
        const float* base = (srci == 0) ? xn1 + (size_t)g*KP1*64
                          : (srci == 1) ? xn2 + (size_t)g*KP2*64
                                        : t3  + (size_t)g*KP2*64;
        int K = (srci == 0) ? KP1 : KP2;
        float pm = -3.402823466e38f, ps = 0.f;
        for (int i = grp; i < K; i += 4){
            float v = base[(size_t)i*64 + f];
            pm = fmaxf(pm, v); ps += v;
        }
        sA[grp*64 + f] = pm; sB[grp*64 + f] = ps;
        __syncthreads();
        if (t < 64){
            float mx = fmaxf(fmaxf(sA[f], sA[64+f]), fmaxf(sA[128+f], sA[192+f]));
            float sm = sB[f] + sB[64+f] + sB[128+f] + sB[192+f];
            accM += fmaxf(mx, 0.f);
            accE += fmaxf(sm/(float)K, 0.f);
        }
        __syncthreads();
    }
    if (t < 64){ rr[f] = accM; rr[64+f] = accE; }
    __syncthreads();
    if (t < 64){
        float a = lb1[t];
        #pragma unroll 8
        for (int q = 0; q < 128; q++) a += lw1[(size_t)t*128 + q]*rr[q];
        h1[t] = fmaxf(a, 0.f);
    }
    __syncthreads();
    if (t < 32){
        float a = lb2[t];
        #pragma unroll 8
        for (int q = 0; q < 64; q++) a += lw2[(size_t)t*64 + q]*h1[q];
        h2[t] = fmaxf(a, 0.f);
    }
    __syncthreads();
    if (t < NCLS){
        float a = lb3[t];
        #pragma unroll
        for (int q = 0; q < 32; q++) a += lw3[(size_t)t*32 + q]*h2[q];
        lg[t] = a;
    }
    __syncthreads();
    if (t == 0){
        float mx = lg[0];
        for (int c = 1; c < NCLS; c++) mx = fmaxf(mx, lg[c]);
        float sm = 0.f;
        for (int c = 0; c < NCLS; c++) sm += expf(lg[c] - mx);
        float lse = mx + logf(sm);
        for (int c = 0; c < NCLS; c++) out[g*NCLS + c] = lg[c] - lse;
    }
}

// ---------------- host launcher ----------------
extern "C" void kernel_launch(void* const* d_in, const int* in_sizes, int n_in,
                              void* d_out, int out_size){
    const float* x    = (const float*)d_in[0];
    const int*   ei   = (const int*)  d_in[1];
    const float* W1   = (const float*)d_in[2];
    const float* b1   = (const float*)d_in[3];
    const float* W2   = (const float*)d_in[4];
    const float* b2   = (const float*)d_in[5];
    const float* W3   = (const float*)d_in[6];
    const float* b3   = (const float*)d_in[7];
    const float* att1 = (const float*)d_in[8];
    const float* att2 = (const float*)d_in[9];
    const float* lw1  = (const float*)d_in[10];
    const float* lb1  = (const float*)d_in[11];
    const float* lw2  = (const float*)d_in[12];
    const float* lb2  = (const float*)d_in[13];
    const float* lw3  = (const float*)d_in[14];
    const float* lb3  = (const float*)d_in[15];
    float* out = (float*)d_out;
    int E = in_sizes[1]/2;

    unsigned* bm; int* lidx;
    float *s, *u, *t1, *dis, *score, *a1, *a2, *xn1, *adj2, *t2, *xn2, *adj3, *t3;
    cudaGetSymbolAddress((void**)&bm,    g_bm);
    cudaGetSymbolAddress((void**)&s,     g_s);
    cudaGetSymbolAddress((void**)&u,     g_u);
    cudaGetSymbolAddress((void**)&t1,    g_t1);
    cudaGetSymbolAddress((void**)&dis,   g_dis);
    cudaGetSymbolAddress((void**)&score, g_score);
    cudaGetSymbolAddress((void**)&lidx,  g_lidx);
    cudaGetSymbolAddress((void**)&a1,    g_a1);
    cudaGetSymbolAddress((void**)&a2,    g_a2);
    cudaGetSymbolAddress((void**)&xn1,   g_xn1);
    cudaGetSymbolAddress((void**)&adj2,  g_adj2);
    cudaGetSymbolAddress((void**)&t2,    g_t2);
    cudaGetSymbolAddress((void**)&xn2,   g_xn2);
    cudaGetSymbolAddress((void**)&adj3,  g_adj3);
    cudaGetSymbolAddress((void**)&t3,    g_t3);

    // layer 1 (sparse bitmap; scatter fused into prep1, bm pre-zeroed invariant)
    k_prep1   <<<NN1/8, 256>>>(x, W1, b1, ei, E, bm, s, u);
    k_agg1    <<<NN1/2, 256>>>(bm, s, u, t1, dis);
    k_score1  <<<NN1/2, 256>>>(bm, s, t1, dis, score);
    k_sel<NPG1,KP1><<<NB, NPG1>>>(score, t1, att1, lidx, a1, a2, xn1);
    k_adjb1   <<<NB*KP1, KP1>>>(lidx, a1, a2, bm, s, adj2);
    // layer 2 (dense 128); k_linear also restores bm==0 invariant
    k_linear  <<<NN2/8, 256>>>(xn1, W2, b2, u, bm);
    k_aggT<KP1>  <<<NB*KP1/16, 256>>>(adj2, u, t2, dis);
    k_scoreT<KP1><<<NB*KP1/16, 256>>>(adj2, t2, dis, score);
    k_sel<KP1,KP2><<<NB, KP1>>>(score, t2, att2, lidx, a1, a2, xn2);
    k_adjb2   <<<NB*KP2, KP2>>>(lidx, a1, a2, adj2, adj3);
    // layer 3 (dense 64)
    k_linear  <<<NN3/8, 256>>>(xn2, W3, b3, u, (unsigned*)0);
    k_aggT<KP2><<<NB*KP2/16, 256>>>(adj3, u, t3, dis);
    // readout + MLP
    k_final   <<<NB, 256>>>(xn1, xn2, t3, lw1, lb1, lw2, lb2, lw3, lb3, out);
}

// round 17
// speedup vs baseline: 1.1715x; 1.1416x over previous
#include <cuda_runtime.h>
#include <math.h>

#define NB     32
#define NPG1   256
#define NFEATD 128
#define NHID   64
#define KP1    128
#define KP2    64
#define NN1    (NB*NPG1)   // 8192
#define NN2    (NB*KP1)    // 4096
#define NN3    (NB*KP2)    // 2048
#define NCLS   6
#define PROJ_MAX 0.996f
#define MINN   1e-15f
#define AART   3.1063030f   // artanh(0.996)

// ---------------- device scratch ----------------
__device__ unsigned g_bm[NN1*8];        // layer-1 bitmap; ALWAYS zero at kernel_launch entry
__device__ float g_s[NN1];
__device__ float g_u[NN1*NHID];
__device__ float g_t1[NN1*NHID];
__device__ float g_dis[NN1];
__device__ float g_score[NN1];
__device__ int   g_lidx[NB*KP1];
__device__ float g_tval[NB*KP1];
__device__ float g_a1[NB*KP1];
__device__ float g_a2[NB*KP1];
__device__ float g_xn1[NN2*NHID];
__device__ float g_adj2[NB*KP1*KP1];
__device__ float g_t2[NN2*NHID];
__device__ float g_xn2[NN3*NHID];
__device__ float g_adj3[NB*KP2*KP2];
__device__ float g_t3[NN3*NHID];

// ---------------- helpers ----------------
__device__ __forceinline__ float artanh_(float x){
    x = fminf(fmaxf(x, -1.0f + 1e-7f), 1.0f - 1e-7f);
    return 0.5f*(log1pf(x) - log1pf(-x));
}
__device__ __forceinline__ float warpSum(float v){
    #pragma unroll
    for (int o = 16; o; o >>= 1) v += __shfl_xor_sync(0xffffffffu, v, o);
    return v;
}

__device__ __forceinline__ void hyp_tail(float mx0, float mx1, float xn,
                                         const float* __restrict__ bb, int l,
                                         float* __restrict__ up){
    float mxn = fmaxf(sqrtf(warpSum(mx0*mx0 + mx1*mx1)), MINN);
    float tv  = tanhf(mxn/xn*artanh_(xn));
    float hs  = tv/mxn;
    float h0 = mx0*hs, h1 = mx1*hs;
    float hn = tv;
    if (hn > PROJ_MAX){ float c = PROJ_MAX/hn; h0 *= c; h1 *= c; hn = PROJ_MAX; }
    float x2 = hn*hn;
    float b0 = bb[l], b1 = bb[l+32];
    float bn = fmaxf(sqrtf(warpSum(b0*b0 + b1*b1)), MINN);
    float tb = tanhf(bn);
    float hbs = tb/bn, hbn = tb;
    if (tb > PROJ_MAX){ hbs = PROJ_MAX/bn; hbn = PROJ_MAX; }
    float hb0 = b0*hbs, hb1 = b1*hbs;
    float y2 = hbn*hbn;
    float xy = warpSum(h0*hb0 + h1*hb1);
    float ca = 1.f + 2.f*xy + y2, cb = 1.f - x2;
    float den = fmaxf(1.f + 2.f*xy + x2*y2, MINN);
    float r0 = (ca*h0 + cb*hb0)/den, r1 = (ca*h1 + cb*hb1)/den;
    float rn = fmaxf(sqrtf(warpSum(r0*r0 + r1*r1)), MINN);
    float pn = rn, psc = 1.f;
    if (rn > PROJ_MAX){ psc = PROJ_MAX/rn; pn = PROJ_MAX; }
    float ls = artanh_(pn)/pn*psc;
    up[l] = r0*ls; up[l+32] = r1*ls;
}

__device__ __forceinline__ void agg_epi(int node, float a0, float a1, float deg,
                                        float* __restrict__ tout, float* __restrict__ dis, int l){
    float n1 = sqrtf(warpSum(a0*a0 + a1*a1));
    float s1 = (n1 > AART) ? AART/n1 : 1.f;
    float w0 = fmaxf(a0*s1, 0.f), w1 = fmaxf(a1*s1, 0.f);
    float n2 = sqrtf(warpSum(w0*w0 + w1*w1));
    float s2 = (n2 > AART) ? AART/n2 : 1.f;
    tout[(size_t)node*64 + l]      = w0*s2;
    tout[(size_t)node*64 + l + 32] = w1*s2;
    if (l == 0) dis[node] = (deg > 0.f) ? rsqrtf(deg) : 0.f;
}

// ---------------- K1: edge scatter (bm pre-zeroed invariant) + row sums + to_hyp + HypLinear ----------------
__global__ void k_prep1(const float* __restrict__ x, const float* __restrict__ W1,
                        const float* __restrict__ bb, const int* __restrict__ ei, int E,
                        unsigned* __restrict__ bm, float* __restrict__ s, float* __restrict__ u){
    __shared__ float Wt[128*64];
    int tid = threadIdx.x;
    for (int e = blockIdx.x*256 + tid; e < E; e += 1024*256){
        int r = ei[e], c = ei[E + e];
        int lc = c & 255;
        atomicOr(&bm[(size_t)r*8 + (lc >> 5)], 1u << (lc & 31));
    }
    for (int e = tid; e < 128*64; e += 256){
        int j = e >> 7, k = e & 127;
        Wt[k*64 + j] = W1[e];
    }
    __syncthreads();
    int w = tid >> 5, l = tid & 31;
    int node = blockIdx.x*8 + w;
    const float* xp = x + (size_t)node*128;
    float xq[4];
    #pragma unroll
    for (int q = 0; q < 4; q++) xq[q] = xp[l + 32*q];
    float ssum = warpSum(xq[0]+xq[1]+xq[2]+xq[3]);
    if (l == 0) s[node] = ssum;
    float n0 = fmaxf(sqrtf(warpSum(xq[0]*xq[0]+xq[1]*xq[1]+xq[2]*xq[2]+xq[3]*xq[3])), MINN);
    float th = tanhf(n0);
    float xsc, xn;
    if (th > PROJ_MAX){ xsc = PROJ_MAX/n0; xn = PROJ_MAX; } else { xsc = th/n0; xn = th; }
    xn = fmaxf(xn, MINN);
    #pragma unroll
    for (int q = 0; q < 4; q++) xq[q] *= xsc;
    float mx0 = 0.f, mx1 = 0.f;
    #pragma unroll
    for (int q = 0; q < 4; q++){
        float xv = xq[q];
        for (int kk = 0; kk < 32; kk++){
            float xk = __shfl_sync(0xffffffffu, xv, kk);
            int k = q*32 + kk;
            mx0 += xk*Wt[k*64 + l];
            mx1 += xk*Wt[k*64 + l + 32];
        }
    }
    hyp_tail(mx0, mx1, xn, bb, l, u + (size_t)node*64);
}

// ---------------- K3: sparse layer-1 HypAgg (R10 plain one-warp form) ----------------
__global__ void k_agg1(const unsigned* __restrict__ bm, const float* __restrict__ s,
                       const float* __restrict__ u, float* __restrict__ tout,
                       float* __restrict__ dis){
    int w = threadIdx.x >> 5, l = threadIdx.x & 31;
    int node = blockIdx.x*8 + w;
    int g = node >> 8;
    const float* ug = u + ((size_t)(g << 8))*64;
    const float* sg = s + (g << 8);
    float sn = sg[node & 255];
    float a0 = 0.f, a1 = 0.f, deg = 0.f;
    #pragma unroll
    for (int w8 = 0; w8 < 8; w8++){
        unsigned bits = bm[(size_t)node*8 + w8];
        while (bits){
            int b = __ffs(bits) - 1; bits &= bits - 1;
            int c = (w8 << 5) | b;
            float wv = 0.5f*(sn + sg[c]);
            a0 += wv*ug[(size_t)c*64 + l];
            a1 += wv*ug[(size_t)c*64 + l + 32];
            deg += wv;
        }
    }
    agg_epi(node, a0, a1, deg, tout, dis, l);
}

// ---------------- K4: sparse layer-1 node information score ----------------
__global__ void k_score1(const unsigned* __restrict__ bm, const float* __restrict__ s,
                         const float* __restrict__ t, const float* __restrict__ dis,
                         float* __restrict__ score){
    int w = threadIdx.x >> 5, l = threadIdx.x & 31;
    int node = blockIdx.x*8 + w;
    int g = node >> 8;
    const float* tg = t + ((size_t)(g << 8))*64;
    const float* sg = s + (g << 8);
    const float* dg = dis + (g << 8);
    float sn = sg[node & 255];
    float dn = dg[node & 255];
    float a0 = 0.f, a1 = 0.f;
    #pragma unroll
    for (int w8 = 0; w8 < 8; w8++){
        unsigned bits = bm[(size_t)node*8 + w8];
        while (bits){
            int b = __ffs(bits) - 1; bits &= bits - 1;
            int c = (w8 << 5) | b;
            float wv = 0.5f*(sn + sg[c])*dg[c];
            a0 += wv*tg[(size_t)c*64 + l];
            a1 += wv*tg[(size_t)c*64 + l + 32];
        }
    }
    float tr0 = tg[(size_t)(node & 255)*64 + l];
    float tr1 = tg[(size_t)(node & 255)*64 + l + 32];
    float d = fabsf(tr0 - dn*a0) + fabsf(tr1 - dn*a1);
    float sc = warpSum(d);
    if (l == 0) score[node] = sc;
}

// ---------------- K5: rank-only top-k selection (cheap) ----------------
template<int NPG, int K>
__global__ void k_sel(const float* __restrict__ score, int* __restrict__ lidx,
                      float* __restrict__ tval){
    __shared__ float key[NPG];
    int g = blockIdx.x, t = threadIdx.x;          // blockDim == NPG
    key[t] = score[g*NPG + t];
    __syncthreads();
    float kt = key[t];
    int rank = 0;
    #pragma unroll 8
    for (int p = 0; p < NPG; p++){
        float kp = key[p];
        rank += (kp > kt || (kp == kt && p < t)) ? 1 : 0;
    }
    if (rank < K){
        lidx[g*K + rank] = t;
        tval[g*K + rank] = tanhf(kt);
    }
}

// ---------------- K7: fused gather + att dots + to_hyp + HypLinear ----------------
// One warp per selected node: coalesced read of t[li], scale by tv,
// writes xn (for readout), a1/a2 (for adjacency build), u (next layer input).
template<int SRCN, int K>
__global__ void k_linsel(const float* __restrict__ tin, const int* __restrict__ lidx,
                         const float* __restrict__ tval, const float* __restrict__ att,
                         const float* __restrict__ W, const float* __restrict__ bb,
                         float* __restrict__ xnb, float* __restrict__ a1,
                         float* __restrict__ a2, float* __restrict__ u){
    __shared__ float Wt[64*64];
    __shared__ float satt[128];
    int tid = threadIdx.x;
    for (int e = tid; e < 4096; e += 256){
        int j = e >> 6, k = e & 63;
        Wt[k*64 + j] = W[e];
    }
    if (tid < 128) satt[tid] = att[tid];
    __syncthreads();
    int w = tid >> 5, l = tid & 31;
    int node = blockIdx.x*8 + w;                  // in [0, NB*K)
    int g = node / K;
    int li = lidx[node];
    float tv = tval[node];
    const float* src = tin + ((size_t)g*SRCN + li)*64;
    float x0 = src[l]*tv, x1 = src[l+32]*tv;
    xnb[(size_t)node*64 + l] = x0;
    xnb[(size_t)node*64 + l + 32] = x1;
    float d1 = warpSum(x0*satt[l] + x1*satt[l+32]);
    float d2 = warpSum(x0*satt[64+l] + x1*satt[64+l+32]);
    if (l == 0){ a1[node] = d1; a2[node] = d2; }
    // to_hyp
    float n0 = fmaxf(sqrtf(warpSum(x0*x0 + x1*x1)), MINN);
    float th = tanhf(n0);
    float xsc, xn;
    if (th > PROJ_MAX){ xsc = PROJ_MAX/n0; xn = PROJ_MAX; } else { xsc = th/n0; xn = th; }
    xn = fmaxf(xn, MINN);
    x0 *= xsc; x1 *= xsc;
    float mx0 = 0.f, mx1 = 0.f;
    #pragma unroll
    for (int q = 0; q < 2; q++){
        float xv = q ? x1 : x0;
        for (int kk = 0; kk < 32; kk++){
            float xk = __shfl_sync(0xffffffffu, xv, kk);
            int k = q*32 + kk;
            mx0 += xk*Wt[k*64 + l];
            mx1 += xk*Wt[k*64 + l + 32];
        }
    }
    hyp_tail(mx0, mx1, xn, bb, l, u + (size_t)node*64);
}

// ---------------- K6a: build adj2 from bitmap ----------------
__global__ void k_adjb1(const int* __restrict__ lidx, const float* __restrict__ a1,
                        const float* __restrict__ a2, const unsigned* __restrict__ bm,
                        const float* __restrict__ s, float* __restrict__ adj2){
    int bi = blockIdx.x;             // g*128 + i
    int g = bi >> 7;
    int j = threadIdx.x;             // 128
    int li = lidx[bi];
    float a1i = a1[bi];
    int lj = lidx[(g << 7) + j];
    float ev = fmaxf(a1i + a2[(g << 7) + j], 0.f);
    unsigned word = bm[((size_t)(g << 8) + li)*8 + (lj >> 5)];
    float old = ((word >> (lj & 31)) & 1u) ? 0.5f*(s[(g << 8) + li] + s[(g << 8) + lj]) : 0.f;
    adj2[(size_t)bi*128 + j] = ev + old;
}

// ---------------- K6b: build adj3 from dense adj2 ----------------
__global__ void k_adjb2(const int* __restrict__ lidx, const float* __restrict__ a1,
                        const float* __restrict__ a2, const float* __restrict__ oldadj,
                        float* __restrict__ adj3){
    int bi = blockIdx.x;             // g*64 + i
    int g = bi >> 6;
    int j = threadIdx.x;             // 64
    int li = lidx[bi];
    float a1i = a1[bi];
    int lj = lidx[(g << 6) + j];
    float ev = fmaxf(a1i + a2[(g << 6) + j], 0.f);
    float old = oldadj[((size_t)(g << 7) + li)*128 + lj];
    adj3[(size_t)bi*64 + j] = ev + old;
}

// ---------------- dense HypAgg, 2 rows/warp (+optional bitmap re-zero) ----------------
template<int NPG>
__global__ void k_aggT(const float* __restrict__ adj, const float* __restrict__ u,
                       float* __restrict__ tout, float* __restrict__ dis,
                       unsigned* __restrict__ bmz){
    constexpr int TPG = NPG/16;
    __shared__ float ush[NPG*64];
    if (bmz){   // restore bm==0 invariant (all bm readers upstream in stream order)
        int gt = blockIdx.x*256 + threadIdx.x;
        if (gt < NN1*8) bmz[gt] = 0u;
    }
    int g = blockIdx.x / TPG, rt = blockIdx.x % TPG;
    int w = threadIdx.x >> 5, l = threadIdx.x & 31;
    int rbase = rt*16 + w*2;
    const float* adjg = adj + (size_t)g*NPG*NPG;
    const float* ug   = u   + (size_t)g*NPG*64;
    {
        const float4* src = (const float4*)ug;
        float4* dst = (float4*)ush;
        for (int e = threadIdx.x; e < NPG*16; e += 256) dst[e] = src[e];
    }
    __syncthreads();
    const float* r0p = adjg + (size_t)rbase*NPG;
    const float* r1p = r0p + NPG;
    float a00=0,a01=0,a10=0,a11=0,d0=0,d1=0;
    #pragma unroll 4
    for (int m = 0; m < NPG; m += 4){
        float4 v0 = *(const float4*)(r0p + m);
        float4 v1 = *(const float4*)(r1p + m);
        float ar0[4] = {v0.x, v0.y, v0.z, v0.w};
        float ar1[4] = {v1.x, v1.y, v1.z, v1.w};
        #pragma unroll
        for (int q = 0; q < 4; q++){
            float u0 = ush[(m+q)*64 + l];
            float u1 = ush[(m+q)*64 + l + 32];
            a00 += ar0[q]*u0; a01 += ar0[q]*u1; d0 += ar0[q];
            a10 += ar1[q]*u0; a11 += ar1[q]*u1; d1 += ar1[q];
        }
    }
    int nb = g*NPG + rbase;
    agg_epi(nb,   a00, a01, d0, tout, dis, l);
    agg_epi(nb+1, a10, a11, d1, tout, dis, l);
}

// ---------------- dense node information score, 2 rows/warp ----------------
template<int NPG>
__global__ void k_scoreT(const float* __restrict__ adj, const float* __restrict__ t,
                         const float* __restrict__ dis, float* __restrict__ score){
    constexpr int TPG = NPG/16;
    __shared__ float tsh[NPG*64];
    int g = blockIdx.x / TPG, rt = blockIdx.x % TPG;
    int w = threadIdx.x >> 5, l = threadIdx.x & 31;
    int rbase = rt*16 + w*2;
    const float* adjg = adj + (size_t)g*NPG*NPG;
    const float* tg   = t   + (size_t)g*NPG*64;
    const float* disg = dis + (size_t)g*NPG;
    {
        const float4* src = (const float4*)tg;
        float4* dst = (float4*)tsh;
        for (int e = threadIdx.x; e < NPG*16; e += 256){
            float4 v = src[e];
            float dm = disg[e >> 4];
            v.x *= dm; v.y *= dm; v.z *= dm; v.w *= dm;
            dst[e] = v;
        }
    }
    float tr0 = tg[(size_t)rbase*64 + l],     tr1 = tg[(size_t)rbase*64 + l + 32];
    float sr0 = tg[(size_t)(rbase+1)*64 + l], sr1 = tg[(size_t)(rbase+1)*64 + l + 32];
    float dr0 = disg[rbase], dr1 = disg[rbase+1];
    __syncthreads();
    const float* r0p = adjg + (size_t)rbase*NPG;
    const float* r1p = r0p + NPG;
    float a00=0,a01=0,a10=0,a11=0;
    #pragma unroll 4
    for (int m = 0; m < NPG; m += 4){
        float4 v0 = *(const float4*)(r0p + m);
        float4 v1 = *(const float4*)(r1p + m);
        float ar0[4] = {v0.x, v0.y, v0.z, v0.w};
        float ar1[4] = {v1.x, v1.y, v1.z, v1.w};
        #pragma unroll
        for (int q = 0; q < 4; q++){
            float u0 = tsh[(m+q)*64 + l];
            float u1 = tsh[(m+q)*64 + l + 32];
            a00 += ar0[q]*u0; a01 += ar0[q]*u1;
            a10 += ar1[q]*u0; a11 += ar1[q]*u1;
        }
    }
    float d0 = fabsf(tr0 - dr0*a00) + fabsf(tr1 - dr0*a01);
    float d1 = fabsf(sr0 - dr1*a10) + fabsf(sr1 - dr1*a11);
    float sc0 = warpSum(d0), sc1 = warpSum(d1);
    if (l == 0){ score[g*NPG + rbase] = sc0; score[g*NPG + rbase + 1] = sc1; }
}

// ---------------- K8: readouts + MLP head + log_softmax ----------------
__global__ void k_final(const float* __restrict__ xn1, const float* __restrict__ xn2,
                        const float* __restrict__ t3,
                        const float* __restrict__ lw1, const float* __restrict__ lb1,
                        const float* __restrict__ lw2, const float* __restrict__ lb2,
                        const float* __restrict__ lw3, const float* __restrict__ lb3,
                        float* __restrict__ out){
    __shared__ float sA[4*64], sB[4*64], rr[128], h1[64], h2[32], lg[NCLS];
    int g = blockIdx.x, t = threadIdx.x;
    int f = t & 63, grp = t >> 6;
    float accM = 0.f, accE = 0.f;
    #pragma unroll
    for (int srci = 0; srci < 3; srci++){
        const float* base = (srci == 0) ? xn1 + (size_t)g*KP1*64
                          : (srci == 1) ? xn2 + (size_t)g*KP2*64
                                        : t3  + (size_t)g*KP2*64;
        int K = (srci == 0) ? KP1 : KP2;
        float pm = -3.402823466e38f, ps = 0.f;
        for (int i = grp; i < K; i += 4){
            float v = base[(size_t)i*64 + f];
            pm = fmaxf(pm, v); ps += v;
        }
        sA[grp*64 + f] = pm; sB[grp*64 + f] = ps;
        __syncthreads();
        if (t < 64){
            float mx = fmaxf(fmaxf(sA[f], sA[64+f]), fmaxf(sA[128+f], sA[192+f]));
            float sm = sB[f] + sB[64+f] + sB[128+f] + sB[192+f];
            accM += fmaxf(mx, 0.f);
            accE += fmaxf(sm/(float)K, 0.f);
        }
        __syncthreads();
    }
    if (t < 64){ rr[f] = accM; rr[64+f] = accE; }
    __syncthreads();
    if (t < 64){
        float a = lb1[t];
        #pragma unroll 8
        for (int q = 0; q < 128; q++) a += lw1[(size_t)t*128 + q]*rr[q];
        h1[t] = fmaxf(a, 0.f);
    }
    __syncthreads();
    if (t < 32){
        float a = lb2[t];
        #pragma unroll 8
        for (int q = 0; q < 64; q++) a += lw2[(size_t)t*64 + q]*h1[q];
        h2[t] = fmaxf(a, 0.f);
    }
    __syncthreads();
    if (t < NCLS){
        float a = lb3[t];
        #pragma unroll
        for (int q = 0; q < 32; q++) a += lw3[(size_t)t*32 + q]*h2[q];
        lg[t] = a;
    }
    __syncthreads();
    if (t == 0){
        float mx = lg[0];
        for (int c = 1; c < NCLS; c++) mx = fmaxf(mx, lg[c]);
        float sm = 0.f;
        for (int c = 0; c < NCLS; c++) sm += expf(lg[c] - mx);
        float lse = mx + logf(sm);
        for (int c = 0; c < NCLS; c++) out[g*NCLS + c] = lg[c] - lse;
    }
}

// ---------------- host launcher ----------------
extern "C" void kernel_launch(void* const* d_in, const int* in_sizes, int n_in,
                              void* d_out, int out_size){
    const float* x    = (const float*)d_in[0];
    const int*   ei   = (const int*)  d_in[1];
    const float* W1   = (const float*)d_in[2];
    const float* b1   = (const float*)d_in[3];
    const float* W2   = (const float*)d_in[4];
    const float* b2   = (const float*)d_in[5];
    const float* W3   = (const float*)d_in[6];
    const float* b3   = (const float*)d_in[7];
    const float* att1 = (const float*)d_in[8];
    const float* att2 = (const float*)d_in[9];
    const float* lw1  = (const float*)d_in[10];
    const float* lb1  = (const float*)d_in[11];
    const float* lw2  = (const float*)d_in[12];
    const float* lb2  = (const float*)d_in[13];
    const float* lw3  = (const float*)d_in[14];
    const float* lb3  = (const float*)d_in[15];
    float* out = (float*)d_out;
    int E = in_sizes[1]/2;

    unsigned* bm; int* lidx;
    float *s, *u, *t1, *dis, *score, *tval, *a1, *a2, *xn1, *adj2, *t2, *xn2, *adj3, *t3;
    cudaGetSymbolAddress((void**)&bm,    g_bm);
    cudaGetSymbolAddress((void**)&s,     g_s);
    cudaGetSymbolAddress((void**)&u,     g_u);
    cudaGetSymbolAddress((void**)&t1,    g_t1);
    cudaGetSymbolAddress((void**)&dis,   g_dis);
    cudaGetSymbolAddress((void**)&score, g_score);
    cudaGetSymbolAddress((void**)&lidx,  g_lidx);
    cudaGetSymbolAddress((void**)&tval,  g_tval);
    cudaGetSymbolAddress((void**)&a1,    g_a1);
    cudaGetSymbolAddress((void**)&a2,    g_a2);
    cudaGetSymbolAddress((void**)&xn1,   g_xn1);
    cudaGetSymbolAddress((void**)&adj2,  g_adj2);
    cudaGetSymbolAddress((void**)&t2,    g_t2);
    cudaGetSymbolAddress((void**)&xn2,   g_xn2);
    cudaGetSymbolAddress((void**)&adj3,  g_adj3);
    cudaGetSymbolAddress((void**)&t3,    g_t3);

    // layer 1 (sparse bitmap; scatter fused into prep1, bm pre-zeroed invariant)
    k_prep1   <<<NN1/8, 256>>>(x, W1, b1, ei, E, bm, s, u);
    k_agg1    <<<NN1/8, 256>>>(bm, s, u, t1, dis);
    k_score1  <<<NN1/8, 256>>>(bm, s, t1, dis, score);
    k_sel<NPG1,KP1><<<NB, NPG1>>>(score, lidx, tval);
    k_linsel<NPG1,KP1><<<NN2/8, 256>>>(t1, lidx, tval, att1, W2, b2, xn1, a1, a2, u);
    k_adjb1   <<<NB*KP1, KP1>>>(lidx, a1, a2, bm, s, adj2);
    // layer 2 (dense 128); k_aggT<KP1> restores bm==0 invariant
    k_aggT<KP1>  <<<NB*KP1/16, 256>>>(adj2, u, t2, dis, bm);
    k_scoreT<KP1><<<NB*KP1/16, 256>>>(adj2, t2, dis, score);
    k_sel<KP1,KP2><<<NB, KP1>>>(score, lidx, tval);
    k_linsel<KP1,KP2><<<NN3/8, 256>>>(t2, lidx, tval, att2, W3, b3, xn2, a1, a2, u);
    k_adjb2   <<<NB*KP2, KP2>>>(lidx, a1, a2, adj2, adj3);
    // layer 3 (dense 64)
    k_aggT<KP2><<<NB*KP2/16, 256>>>(adj3, u, t3, dis, (unsigned*)0);
    // readout + MLP
    k_final   <<<NB, 256>>>(xn1, xn2, t3, lw1, lb1, lw2, lb2, lw3, lb3, out);
}